// round 12
// baseline (speedup 1.0000x reference)
#include <cuda_runtime.h>
#include <cuda_fp16.h>
#include <math.h>
#include <stdint.h>

// ---------------- problem constants ----------------
#define BSZ     4
#define NQ      1024
#define NK      2048
#define DIM     1024
#define HEADS   16
#define HD      64
#define HIDDEN  4096
#define MQ      (BSZ*NQ)   // 4096
#define MK      (BSZ*NK)   // 8192

// ---------------- scratch ----------
__device__ __align__(128) __half g_qn  [(size_t)MQ * DIM];
__device__ __align__(128) __half g_q   [(size_t)MQ * DIM];
__device__ __align__(128) __half g_k   [(size_t)MK * DIM];   // reused as fp32 p0 after attn
__device__ __align__(128) __half g_v   [(size_t)MK * DIM];   // reused as fp32 p1 after attn
__device__ __align__(128) __half g_ctx [(size_t)MQ * DIM];
__device__ __align__(128) __half g_h1  [(size_t)MQ * HIDDEN];
__device__ __align__(128) __half g_embh[(size_t)MK * DIM];
__device__ __align__(128) __half g_wqt [(size_t)DIM * DIM];
__device__ __align__(128) __half g_wkt [(size_t)DIM * DIM];
__device__ __align__(128) __half g_wvt [(size_t)DIM * DIM];
__device__ __align__(128) __half g_wot [(size_t)DIM * DIM];
__device__ __align__(128) __half g_w1t [(size_t)DIM * HIDDEN];
__device__ __align__(128) __half g_w2t [(size_t)HIDDEN * DIM];

// ==================== helpers ====================
__device__ __forceinline__ float gelu_exact(float x) {
    return 0.5f * x * (1.0f + erff(x * 0.70710678118654752f));
}
__device__ __forceinline__ void cp16(void* s, const void* g) {
    uint32_t sa = (uint32_t)__cvta_generic_to_shared(s);
    asm volatile("cp.async.ca.shared.global [%0], [%1], 16;" :: "r"(sa), "l"(g));
}
__device__ __forceinline__ void mma_f16(float d[4], const uint32_t a[4], const uint32_t b[2]) {
    asm volatile(
        "mma.sync.aligned.m16n8k16.row.col.f32.f16.f16.f32 "
        "{%0,%1,%2,%3}, {%4,%5,%6,%7}, {%8,%9}, {%0,%1,%2,%3};"
        : "+f"(d[0]), "+f"(d[1]), "+f"(d[2]), "+f"(d[3])
        : "r"(a[0]), "r"(a[1]), "r"(a[2]), "r"(a[3]), "r"(b[0]), "r"(b[1]));
}
__device__ __forceinline__ void ldsm_x4(uint32_t& d0, uint32_t& d1,
                                        uint32_t& d2, uint32_t& d3, uint32_t addr) {
    asm volatile("ldmatrix.sync.aligned.m8n8.x4.shared.b16 {%0,%1,%2,%3}, [%4];"
                 : "=r"(d0), "=r"(d1), "=r"(d2), "=r"(d3) : "r"(addr));
}
__device__ __forceinline__ void ldsm_x4_trans(uint32_t& d0, uint32_t& d1,
                                              uint32_t& d2, uint32_t& d3, uint32_t addr) {
    asm volatile("ldmatrix.sync.aligned.m8n8.x4.trans.shared.b16 {%0,%1,%2,%3}, [%4];"
                 : "=r"(d0), "=r"(d1), "=r"(d2), "=r"(d3) : "r"(addr));
}

// ==================== prep: 6 weight transposes + emb conversion =============
__global__ __launch_bounds__(256)
void prep_kernel(const float* wq, const float* wk, const float* wv,
                 const float* wo, const float* w1, const float* w2,
                 const float* emb,
                 __half* wqt, __half* wkt, __half* wvt,
                 __half* wot, __half* w1t, __half* w2t, __half* embh)
{
    int t = blockIdx.x;
    if (t >= 12288) {
        // emb -> half: 1024 blocks, grid-stride over 2M float4
        int i = (t - 12288) * 256 + threadIdx.x;
        int n4 = MK * DIM / 4;
        int stride = 1024 * 256;
        const float4* in = (const float4*)emb;
        __half2* out = (__half2*)embh;
        for (; i < n4; i += stride) {
            float4 v = in[i];
            out[2 * i]     = __floats2half2_rn(v.x, v.y);
            out[2 * i + 1] = __floats2half2_rn(v.z, v.w);
        }
        return;
    }
    __shared__ float tile[32][33];
    const float* in; __half* out; int K, N, lt;
    if (t < 4096) {
        K = DIM; N = DIM; lt = t & 1023;
        int sel = t >> 10;
        in  = sel == 0 ? wq  : sel == 1 ? wk  : sel == 2 ? wv  : wo;
        out = sel == 0 ? wqt : sel == 1 ? wkt : sel == 2 ? wvt : wot;
    } else if (t < 8192) {
        K = DIM; N = HIDDEN; lt = t - 4096; in = w1; out = w1t;
    } else {
        K = HIDDEN; N = DIM; lt = t - 8192; in = w2; out = w2t;
    }
    int tilesX = N >> 5;
    int bx = (lt % tilesX) * 32;
    int by = (lt / tilesX) * 32;
    int tx = threadIdx.x & 31, ty = threadIdx.x >> 5;
    #pragma unroll
    for (int i = 0; i < 32; i += 8)
        tile[ty + i][tx] = in[(size_t)(by + ty + i) * N + bx + tx];
    __syncthreads();
    #pragma unroll
    for (int i = 0; i < 32; i += 8)
        out[(size_t)(bx + ty + i) * K + by + tx] = __float2half_rn(tile[tx][ty + i]);
}

// ==================== LayerNorm (half output) ====================
__global__ __launch_bounds__(256)
void ln_kernel(const float* __restrict__ x, const float* __restrict__ g,
               const float* __restrict__ bt, __half* __restrict__ out)
{
    int row = blockIdx.x;
    int t = threadIdx.x;
    const float4* xr = (const float4*)(x + (size_t)row * DIM);
    float4 v = xr[t];
    float s  = v.x + v.y + v.z + v.w;
    float sq = v.x*v.x + v.y*v.y + v.z*v.z + v.w*v.w;

    #pragma unroll
    for (int off = 16; off; off >>= 1) {
        s  += __shfl_xor_sync(0xffffffffu, s,  off);
        sq += __shfl_xor_sync(0xffffffffu, sq, off);
    }
    __shared__ float ss[8], sqs[8];
    int warp = t >> 5, lane = t & 31;
    if (lane == 0) { ss[warp] = s; sqs[warp] = sq; }
    __syncthreads();
    if (t < 32) {
        float a = (t < 8) ? ss[t]  : 0.f;
        float b = (t < 8) ? sqs[t] : 0.f;
        #pragma unroll
        for (int off = 4; off; off >>= 1) {
            a += __shfl_xor_sync(0xffffffffu, a, off);
            b += __shfl_xor_sync(0xffffffffu, b, off);
        }
        if (t == 0) { ss[0] = a; sqs[0] = b; }
    }
    __syncthreads();
    float mu  = ss[0]  * (1.0f / DIM);
    float var = sqs[0] * (1.0f / DIM) - mu * mu;
    float inv = rsqrtf(var + 1e-5f);

    float4 gv = ((const float4*)g)[t];
    float4 bv = ((const float4*)bt)[t];
    __half2* o2 = (__half2*)(out + (size_t)row * DIM);
    o2[2 * t]     = __floats2half2_rn((v.x - mu) * inv * gv.x + bv.x,
                                      (v.y - mu) * inv * gv.y + bv.y);
    o2[2 * t + 1] = __floats2half2_rn((v.z - mu) * inv * gv.z + bv.z,
                                      (v.w - mu) * inv * gv.w + bv.w);
}

// ==================== split-K reduce: out += p0 + p1 + bias ====================
__global__ __launch_bounds__(256)
void reduce2_kernel(float* __restrict__ out, const float* __restrict__ p0,
                    const float* __restrict__ p1, const float* __restrict__ bias)
{
    int i = blockIdx.x * 256 + threadIdx.x;           // float4 index
    int col4 = (i & (DIM / 4 - 1)) * 4;
    float4 o = ((float4*)out)[i];
    float4 a = ((const float4*)p0)[i];
    float4 b = ((const float4*)p1)[i];
    float4 bb = *(const float4*)(bias + col4);
    o.x += a.x + b.x + bb.x;
    o.y += a.y + b.y + bb.y;
    o.z += a.z + b.z + bb.z;
    o.w += a.w + b.w + bb.w;
    ((float4*)out)[i] = o;
}

// ==================== fp16 GEMM: CTA 128x256, warp 64x64, 1 CTA/SM ===========
// mode: 0 = bias (half out), 1 = bias+gelu (half out),
//       2 = bias+residual (fp32 out), 3 = raw fp32 partial (no bias)
// blockIdx.z in {0,1,2} selects (A,Bt,bias,C); z==2 CTAs with ctaM >= rows2 exit.
#define BM    128
#define BN    256
#define KCH   64
#define SKH   72
#define A_TILE_H (BM * SKH)
#define B_TILE_H (BN * SKH)
#define STAGE_H (A_TILE_H + B_TILE_H)
#define N_STG 3
#define GEMM_SMEM (N_STG * STAGE_H * 2)   // 165888 bytes

__global__ __launch_bounds__(256, 1)
void h16_gemm(int M, int N, int K, int lda, int ldb,
              const __half* __restrict__ A0, const __half* __restrict__ Bt0,
              const float* __restrict__ bias0, const float* __restrict__ res,
              void* __restrict__ C0, int mode,
              const __half* __restrict__ A1, const __half* __restrict__ Bt1,
              const float* __restrict__ bias1, void* __restrict__ C1,
              const __half* __restrict__ A2, const __half* __restrict__ Bt2,
              const float* __restrict__ bias2, void* __restrict__ C2, int rows2)
{
    extern __shared__ __half smh[];

    const __half* A = A0; const __half* Bt = Bt0;
    const float* bias = bias0; void* Cv = C0;
    if (blockIdx.z == 1) { A = A1; Bt = Bt1; bias = bias1; Cv = C1; }
    else if (blockIdx.z == 2) {
        if ((int)blockIdx.y * BM >= rows2) return;
        A = A2; Bt = Bt2; bias = bias2; Cv = C2;
    }

    int tid = threadIdx.x;
    int lane = tid & 31;
    int warp = tid >> 5;
    int warp_m = (warp & 1) * 64;
    int warp_n = (warp >> 1) * 64;
    int r = lane >> 2;
    int c = lane & 3;

    int ctaM = blockIdx.y * BM;
    int ctaN = blockIdx.x * BN;

    const __half* gA = A  + (size_t)ctaM * lda;
    const __half* gB = Bt + (size_t)ctaN * ldb;

    int ldRow = tid >> 3;
    int ldCh  = (tid & 7) * 8;

    const int nk = K / KCH;

    uint32_t smb = (uint32_t)__cvta_generic_to_shared(smh);
    int aRowSel = lane & 15;
    int aKSel   = (lane >> 4) * 8;
    int bNSel   = (lane & 7) + ((lane >> 4) << 3);
    int bKSel   = ((lane >> 3) & 1) * 8;
    uint32_t aBase = smb + (uint32_t)(((warp_m + aRowSel) * SKH + aKSel) * 2);
    uint32_t bBase = smb + (uint32_t)((A_TILE_H + (warp_n + bNSel) * SKH + bKSel) * 2);

    #define ISSUE_STAGE(s, k0)                                                     \
    do {                                                                           \
        __half* sA_ = smh + (s) * STAGE_H;                                         \
        __half* sB_ = sA_ + A_TILE_H;                                              \
        const __half* a_ = gA + (k0);                                              \
        const __half* b_ = gB + (k0);                                              \
        _Pragma("unroll")                                                          \
        for (int j = 0; j < 4; j++) {                                              \
            int row = ldRow + j * 32;                                              \
            cp16(sA_ + (size_t)row * SKH + ldCh, a_ + (size_t)row * lda + ldCh);   \
        }                                                                          \
        _Pragma("unroll")                                                          \
        for (int j = 0; j < 8; j++) {                                              \
            int row = ldRow + j * 32;                                              \
            cp16(sB_ + (size_t)row * SKH + ldCh, b_ + (size_t)row * ldb + ldCh);   \
        }                                                                          \
        asm volatile("cp.async.commit_group;");                                    \
    } while (0)

    ISSUE_STAGE(0, 0);
    if (nk > 1) ISSUE_STAGE(1, KCH);
    else        asm volatile("cp.async.commit_group;");

    float acc[4][8][4] = {};

    for (int kt = 0; kt < nk; kt++) {
        int buf = kt % N_STG;
        if (kt + 1 < nk) asm volatile("cp.async.wait_group 1;");
        else             asm volatile("cp.async.wait_group 0;");
        __syncthreads();

        if (kt + 2 < nk) {
            int s = (kt + 2) % N_STG;
            ISSUE_STAGE(s, (kt + 2) * KCH);
        }

        uint32_t stOff = (uint32_t)(buf * STAGE_H * 2);

        #pragma unroll
        for (int ks = 0; ks < 4; ks++) {
            uint32_t af[4][4], bf[8][2];
            uint32_t kOff = (uint32_t)(ks * 16 * 2);
            #pragma unroll
            for (int mt = 0; mt < 4; mt++)
                ldsm_x4(af[mt][0], af[mt][1], af[mt][2], af[mt][3],
                        aBase + stOff + kOff + (uint32_t)(mt * 16 * SKH * 2));
            #pragma unroll
            for (int np = 0; np < 4; np++)
                ldsm_x4(bf[2 * np][0], bf[2 * np][1], bf[2 * np + 1][0], bf[2 * np + 1][1],
                        bBase + stOff + kOff + (uint32_t)(np * 16 * SKH * 2));
            #pragma unroll
            for (int mt = 0; mt < 4; mt++)
                #pragma unroll
                for (int nt = 0; nt < 8; nt++)
                    mma_f16(acc[mt][nt], af[mt], bf[nt]);
        }
    }
    #undef ISSUE_STAGE

    // ---- epilogue ----
    float*  Cf = (float*)Cv;
    __half* Ch = (__half*)Cv;
    #pragma unroll
    for (int mt = 0; mt < 4; mt++) {
        #pragma unroll
        for (int nt = 0; nt < 8; nt++) {
            int row = ctaM + warp_m + mt * 16 + r;
            int col = ctaN + warp_n + nt * 8 + 2 * c;
            if (mode == 3) {
                *(float2*)(Cf + (size_t)row * N + col) =
                    make_float2(acc[mt][nt][0], acc[mt][nt][1]);
                *(float2*)(Cf + (size_t)(row + 8) * N + col) =
                    make_float2(acc[mt][nt][2], acc[mt][nt][3]);
                continue;
            }
            float b0 = bias[col], b1 = bias[col + 1];
            float v0 = acc[mt][nt][0] + b0;
            float v1 = acc[mt][nt][1] + b1;
            float v2 = acc[mt][nt][2] + b0;
            float v3 = acc[mt][nt][3] + b1;
            if (mode == 2) {
                const float* r0 = res + (size_t)row * N + col;
                const float* r1 = res + (size_t)(row + 8) * N + col;
                v0 += r0[0]; v1 += r0[1];
                v2 += r1[0]; v3 += r1[1];
                *(float2*)(Cf + (size_t)row * N + col)       = make_float2(v0, v1);
                *(float2*)(Cf + (size_t)(row + 8) * N + col) = make_float2(v2, v3);
            } else {
                if (mode == 1) {
                    v0 = gelu_exact(v0); v1 = gelu_exact(v1);
                    v2 = gelu_exact(v2); v3 = gelu_exact(v3);
                }
                *(__half2*)(Ch + (size_t)row * N + col)       = __floats2half2_rn(v0, v1);
                *(__half2*)(Ch + (size_t)(row + 8) * N + col) = __floats2half2_rn(v2, v3);
            }
        }
    }
}

// ==================== fp16 flash attention (3-stage K/V) ======================
#define BQ_T   128
#define TILE_K 64
#define SKKH 72
#define SKVH 72
#define SKPH 72
#define NT_KV (NK / TILE_K)
#define ATT_SMEM ((3*TILE_K*SKKH + 3*TILE_K*SKVH + BQ_T*SKPH) * 2)   // 73728 B

__global__ __launch_bounds__(256, 2)
void attn_mma(const __half* __restrict__ Q, const __half* __restrict__ Kg,
              const __half* __restrict__ Vg, __half* __restrict__ ctx)
{
    extern __shared__ __half smA[];
    __half* KsB = smA;
    __half* VsB = smA + 3 * TILE_K * SKKH;
    __half* Ps  = smA + 3 * TILE_K * (SKKH + SKVH);

    int b = blockIdx.z, h = blockIdx.y, qt = blockIdx.x;
    int tid = threadIdx.x, lane = tid & 31, w = tid >> 5;
    int r = lane >> 2, c = lane & 3;

    const __half* Qb = Q  + ((size_t)(b * NQ + qt * BQ_T)) * DIM + h * HD;
    const __half* Kb = Kg + ((size_t)b * NK) * DIM + h * HD;
    const __half* Vb = Vg + ((size_t)b * NK) * DIM + h * HD;

    #define ATT_ISSUE(s, kt_)                                                      \
    do {                                                                           \
        const __half* kp_ = Kb + (size_t)(kt_) * TILE_K * DIM;                     \
        const __half* vp_ = Vb + (size_t)(kt_) * TILE_K * DIM;                     \
        __half* Kd_ = KsB + (s) * TILE_K * SKKH;                                   \
        __half* Vd_ = VsB + (s) * TILE_K * SKVH;                                   \
        _Pragma("unroll")                                                          \
        for (int i = 0; i < 2; i++) {                                              \
            int idx = tid + i * 256;                                               \
            int row = idx >> 3, ch = (idx & 7) * 8;                                \
            cp16(&Kd_[row * SKKH + ch], kp_ + (size_t)row * DIM + ch);             \
            cp16(&Vd_[row * SKVH + ch], vp_ + (size_t)row * DIM + ch);             \
        }                                                                          \
        asm volatile("cp.async.commit_group;");                                    \
    } while (0)

    ATT_ISSUE(0, 0);
    ATT_ISSUE(1, 1);

    uint32_t qf[4][4];
    {
        const __half2 sc = __floats2half2_rn(0.125f, 0.125f);
        const __half* q0 = Qb + (size_t)(w * 16 + r) * DIM;
        const __half* q1 = Qb + (size_t)(w * 16 + r + 8) * DIM;
        #pragma unroll
        for (int kg = 0; kg < 4; kg++) {
            __half2 a0 = __hmul2(*(const __half2*)(q0 + kg * 16 + 2 * c), sc);
            __half2 a1 = __hmul2(*(const __half2*)(q1 + kg * 16 + 2 * c), sc);
            __half2 a2 = __hmul2(*(const __half2*)(q0 + kg * 16 + 2 * c + 8), sc);
            __half2 a3 = __hmul2(*(const __half2*)(q1 + kg * 16 + 2 * c + 8), sc);
            qf[kg][0] = *(uint32_t*)&a0; qf[kg][1] = *(uint32_t*)&a1;
            qf[kg][2] = *(uint32_t*)&a2; qf[kg][3] = *(uint32_t*)&a3;
        }
    }

    float m0 = -1e30f, m1 = -1e30f, l0 = 0.f, l1 = 0.f;
    float accO[8][4] = {};
    __half* Pw = Ps + (w * 16) * SKPH;
    int l16 = lane & 15, nsel = lane >> 4;

    uint32_t smb = (uint32_t)__cvta_generic_to_shared(smA);
    int bNSel = (lane & 7) + ((lane >> 4) << 3);
    int bKSel = ((lane >> 3) & 1) * 8;
    int aRowSel = lane & 15;
    int aKSel   = (lane >> 4) * 8;
    uint32_t kFragBase = smb + (uint32_t)((bNSel * SKKH + bKSel) * 2);
    uint32_t pFragBase = smb + (uint32_t)((3 * TILE_K * (SKKH + SKVH)
                         + (w * 16 + aRowSel) * SKPH + aKSel) * 2);

    for (int kt = 0; kt < NT_KV; kt++) {
        int buf = kt % 3;
        if (kt + 1 < NT_KV) asm volatile("cp.async.wait_group 1;");
        else                asm volatile("cp.async.wait_group 0;");
        __syncthreads();

        if (kt + 2 < NT_KV) ATT_ISSUE((kt + 2) % 3, kt + 2);

        const __half* Vt = VsB + buf * TILE_K * SKVH;
        uint32_t kStage = (uint32_t)(buf * TILE_K * SKKH * 2);

        float accS[8][4] = {};
        #pragma unroll
        for (int kg = 0; kg < 4; kg++) {
            uint32_t kOff = (uint32_t)(kg * 16 * 2);
            #pragma unroll
            for (int np = 0; np < 4; np++) {
                uint32_t bf0[2], bf1[2];
                ldsm_x4(bf0[0], bf0[1], bf1[0], bf1[1],
                        kFragBase + kStage + kOff + (uint32_t)(np * 16 * SKKH * 2));
                mma_f16(accS[2 * np],     qf[kg], bf0);
                mma_f16(accS[2 * np + 1], qf[kg], bf1);
            }
        }

        float mx0 = -1e30f, mx1 = -1e30f;
        #pragma unroll
        for (int nt = 0; nt < 8; nt++) {
            mx0 = fmaxf(mx0, fmaxf(accS[nt][0], accS[nt][1]));
            mx1 = fmaxf(mx1, fmaxf(accS[nt][2], accS[nt][3]));
        }
        mx0 = fmaxf(mx0, __shfl_xor_sync(0xffffffffu, mx0, 1));
        mx0 = fmaxf(mx0, __shfl_xor_sync(0xffffffffu, mx0, 2));
        mx1 = fmaxf(mx1, __shfl_xor_sync(0xffffffffu, mx1, 1));
        mx1 = fmaxf(mx1, __shfl_xor_sync(0xffffffffu, mx1, 2));
        float mn0 = fmaxf(m0, mx0), mn1 = fmaxf(m1, mx1);
        float f0 = __expf(m0 - mn0), f1 = __expf(m1 - mn1);
        float s0 = 0.f, s1 = 0.f;
        #pragma unroll
        for (int nt = 0; nt < 8; nt++) {
            accS[nt][0] = __expf(accS[nt][0] - mn0);
            accS[nt][1] = __expf(accS[nt][1] - mn0);
            accS[nt][2] = __expf(accS[nt][2] - mn1);
            accS[nt][3] = __expf(accS[nt][3] - mn1);
            s0 += accS[nt][0] + accS[nt][1];
            s1 += accS[nt][2] + accS[nt][3];
        }
        s0 += __shfl_xor_sync(0xffffffffu, s0, 1);
        s0 += __shfl_xor_sync(0xffffffffu, s0, 2);
        s1 += __shfl_xor_sync(0xffffffffu, s1, 1);
        s1 += __shfl_xor_sync(0xffffffffu, s1, 2);
        l0 = l0 * f0 + s0; l1 = l1 * f1 + s1;
        m0 = mn0; m1 = mn1;
        #pragma unroll
        for (int nt = 0; nt < 8; nt++) {
            accO[nt][0] *= f0; accO[nt][1] *= f0;
            accO[nt][2] *= f1; accO[nt][3] *= f1;
        }

        #pragma unroll
        for (int nt = 0; nt < 8; nt++) {
            *(__half2*)&Pw[r * SKPH + nt * 8 + 2 * c] =
                __floats2half2_rn(accS[nt][0], accS[nt][1]);
            *(__half2*)&Pw[(r + 8) * SKPH + nt * 8 + 2 * c] =
                __floats2half2_rn(accS[nt][2], accS[nt][3]);
        }
        __syncwarp();

        #pragma unroll
        for (int kg = 0; kg < 4; kg++) {
            uint32_t af[4];
            ldsm_x4(af[0], af[1], af[2], af[3],
                    pFragBase + (uint32_t)(kg * 16 * 2));
            #pragma unroll
            for (int nt = 0; nt < 8; nt += 2) {
                uint32_t vaddr = (uint32_t)__cvta_generic_to_shared(
                    Vt + (size_t)(kg * 16 + l16) * SKVH + (nt + nsel) * 8);
                uint32_t b0, b1, b2, b3;
                ldsm_x4_trans(b0, b1, b2, b3, vaddr);
                uint32_t bfa[2] = { b0, b1 }, bfb[2] = { b2, b3 };
                mma_f16(accO[nt], af, bfa);
                mma_f16(accO[nt + 1], af, bfb);
            }
        }
        __syncwarp();
    }
    #undef ATT_ISSUE

    float inv0 = 1.f / l0, inv1 = 1.f / l1;
    __half* Cb = ctx + ((size_t)(b * NQ + qt * BQ_T + w * 16)) * DIM + h * HD;
    #pragma unroll
    for (int nt = 0; nt < 8; nt++) {
        *(__half2*)(Cb + (size_t)r * DIM + nt * 8 + 2 * c) =
            __floats2half2_rn(accO[nt][0] * inv0, accO[nt][1] * inv0);
        *(__half2*)(Cb + (size_t)(r + 8) * DIM + nt * 8 + 2 * c) =
            __floats2half2_rn(accO[nt][2] * inv1, accO[nt][3] * inv1);
    }
}

// ==================== launch =================================================
extern "C" void kernel_launch(void* const* d_in, const int* in_sizes, int n_in,
                              void* d_out, int out_size)
{
    const float* tgt  = (const float*)d_in[0];
    const float* emb  = (const float*)d_in[1];
    const float* ln_g = (const float*)d_in[2];
    const float* ln_b = (const float*)d_in[3];
    const float* wq = (const float*)d_in[4];  const float* bq = (const float*)d_in[5];
    const float* wk = (const float*)d_in[6];  const float* bk = (const float*)d_in[7];
    const float* wv = (const float*)d_in[8];  const float* bv = (const float*)d_in[9];
    const float* wo = (const float*)d_in[10]; const float* bo = (const float*)d_in[11];
    const float* w1 = (const float*)d_in[12]; const float* b1 = (const float*)d_in[13];
    const float* w2 = (const float*)d_in[14]; const float* b2 = (const float*)d_in[15];
    float* out = (float*)d_out;

    __half *qn, *q, *k, *v, *ctx, *h1, *embh, *wqt, *wkt, *wvt, *wot, *w1t, *w2t;
    cudaGetSymbolAddress((void**)&qn,   g_qn);
    cudaGetSymbolAddress((void**)&q,    g_q);
    cudaGetSymbolAddress((void**)&k,    g_k);
    cudaGetSymbolAddress((void**)&v,    g_v);
    cudaGetSymbolAddress((void**)&ctx,  g_ctx);
    cudaGetSymbolAddress((void**)&h1,   g_h1);
    cudaGetSymbolAddress((void**)&embh, g_embh);
    cudaGetSymbolAddress((void**)&wqt,  g_wqt);
    cudaGetSymbolAddress((void**)&wkt,  g_wkt);
    cudaGetSymbolAddress((void**)&wvt,  g_wvt);
    cudaGetSymbolAddress((void**)&wot,  g_wot);
    cudaGetSymbolAddress((void**)&w1t,  g_w1t);
    cudaGetSymbolAddress((void**)&w2t,  g_w2t);

    // split-K partial buffers reuse dead K/V storage (each 16MB)
    float* p0 = (float*)k;
    float* p1 = (float*)v;

    cudaFuncSetAttribute(h16_gemm, cudaFuncAttributeMaxDynamicSharedMemorySize, GEMM_SMEM);
    cudaFuncSetAttribute(attn_mma, cudaFuncAttributeMaxDynamicSharedMemorySize, ATT_SMEM);

    // 0) prep: 6 transposes + emb conversion (one launch)
    prep_kernel<<<13312, 256>>>(wq, wk, wv, wo, w1, w2, emb,
                                wqt, wkt, wvt, wot, w1t, w2t, embh);

    // 1) qn = LN(tgt) (half)
    ln_kernel<<<MQ, 256>>>(tgt, ln_g, ln_b, qn);

    // 2-4) K,V,Q fused: z=0 K, z=1 V, z=2 Q (Q only y<32)
    h16_gemm<<<dim3(DIM / BN, MK / BM, 3), 256, GEMM_SMEM>>>(
        MK, DIM, DIM, DIM, DIM,
        embh, wkt, bk, nullptr, (void*)k, 0,
        embh, wvt, bv, (void*)v,
        qn,   wqt, bq, (void*)q, MQ);

    // 5) ctx = softmax(Q K^T / 8) V
    attn_mma<<<dim3(NQ / BQ_T, HEADS, BSZ), 256, ATT_SMEM>>>(q, k, v, ctx);

    // 6) tgt1 = tgt + ctx @ wo + bo -> d_out (fp32)
    h16_gemm<<<dim3(DIM / BN, MQ / BM, 1), 256, GEMM_SMEM>>>(
        MQ, DIM, DIM, DIM, DIM,
        ctx, wot, bo, tgt, (void*)out, 2,
        ctx, wot, bo, (void*)out,
        ctx, wot, bo, (void*)out, MQ);

    // 7) h_in = LN(tgt1) (half)
    ln_kernel<<<MQ, 256>>>(out, ln_g, ln_b, qn);

    // 8) h1 = gelu(h_in @ w1 + b1) (half out)
    h16_gemm<<<dim3(HIDDEN / BN, MQ / BM, 1), 256, GEMM_SMEM>>>(
        MQ, HIDDEN, DIM, DIM, DIM,
        qn, w1t, b1, nullptr, (void*)h1, 1,
        qn, w1t, b1, (void*)h1,
        qn, w1t, b1, (void*)h1, MQ);

    // 9a) MLP2 split-K=2: partials (K halves of 2048, lda/ldb = 4096)
    h16_gemm<<<dim3(DIM / BN, MQ / BM, 2), 256, GEMM_SMEM>>>(
        MQ, DIM, HIDDEN / 2, HIDDEN, HIDDEN,
        h1, w2t, b2, nullptr, (void*)p0, 3,
        h1 + HIDDEN / 2, w2t + HIDDEN / 2, b2, (void*)p1,
        h1, w2t, b2, (void*)p0, MQ);

    // 9b) out += p0 + p1 + b2  (out already holds tgt1)
    reduce2_kernel<<<MQ * DIM / 4 / 256, 256>>>(out, p0, p1, b2);
}

// round 13
// speedup vs baseline: 1.0283x; 1.0283x over previous
#include <cuda_runtime.h>
#include <cuda_fp16.h>
#include <math.h>
#include <stdint.h>

// ---------------- problem constants ----------------
#define BSZ     4
#define NQ      1024
#define NK      2048
#define DIM     1024
#define HEADS   16
#define HD      64
#define HIDDEN  4096
#define MQ      (BSZ*NQ)   // 4096
#define MK      (BSZ*NK)   // 8192

// ---------------- scratch ----------
__device__ __align__(128) __half g_qn  [(size_t)MQ * DIM];
__device__ __align__(128) __half g_q   [(size_t)MQ * DIM];
__device__ __align__(128) __half g_k   [(size_t)MK * DIM];   // reused as fp32 p0 after attn
__device__ __align__(128) __half g_v   [(size_t)MK * DIM];   // reused as fp32 p1 after attn
__device__ __align__(128) __half g_ctx [(size_t)MQ * DIM];
__device__ __align__(128) __half g_h1  [(size_t)MQ * HIDDEN];
__device__ __align__(128) __half g_embh[(size_t)MK * DIM];
__device__ __align__(128) __half g_wqt [(size_t)DIM * DIM];
__device__ __align__(128) __half g_wkt [(size_t)DIM * DIM];
__device__ __align__(128) __half g_wvt [(size_t)DIM * DIM];
__device__ __align__(128) __half g_wot [(size_t)DIM * DIM];
__device__ __align__(128) __half g_w1t [(size_t)DIM * HIDDEN];
__device__ __align__(128) __half g_w2t [(size_t)HIDDEN * DIM];

// ==================== helpers ====================
__device__ __forceinline__ float gelu_exact(float x) {
    return 0.5f * x * (1.0f + erff(x * 0.70710678118654752f));
}
__device__ __forceinline__ void cp16(void* s, const void* g) {
    uint32_t sa = (uint32_t)__cvta_generic_to_shared(s);
    asm volatile("cp.async.ca.shared.global [%0], [%1], 16;" :: "r"(sa), "l"(g));
}
__device__ __forceinline__ void mma_f16(float d[4], const uint32_t a[4], const uint32_t b[2]) {
    asm volatile(
        "mma.sync.aligned.m16n8k16.row.col.f32.f16.f16.f32 "
        "{%0,%1,%2,%3}, {%4,%5,%6,%7}, {%8,%9}, {%0,%1,%2,%3};"
        : "+f"(d[0]), "+f"(d[1]), "+f"(d[2]), "+f"(d[3])
        : "r"(a[0]), "r"(a[1]), "r"(a[2]), "r"(a[3]), "r"(b[0]), "r"(b[1]));
}
__device__ __forceinline__ void ldsm_x4(uint32_t& d0, uint32_t& d1,
                                        uint32_t& d2, uint32_t& d3, uint32_t addr) {
    asm volatile("ldmatrix.sync.aligned.m8n8.x4.shared.b16 {%0,%1,%2,%3}, [%4];"
                 : "=r"(d0), "=r"(d1), "=r"(d2), "=r"(d3) : "r"(addr));
}
__device__ __forceinline__ void ldsm_x4_trans(uint32_t& d0, uint32_t& d1,
                                              uint32_t& d2, uint32_t& d3, uint32_t addr) {
    asm volatile("ldmatrix.sync.aligned.m8n8.x4.trans.shared.b16 {%0,%1,%2,%3}, [%4];"
                 : "=r"(d0), "=r"(d1), "=r"(d2), "=r"(d3) : "r"(addr));
}
__device__ __forceinline__ uint32_t pack_h2(float a, float b) {
    __half2 h = __floats2half2_rn(a, b);
    return *(uint32_t*)&h;
}

// ==================== prep: 6 weight transposes + emb conversion =============
__global__ __launch_bounds__(256)
void prep_kernel(const float* wq, const float* wk, const float* wv,
                 const float* wo, const float* w1, const float* w2,
                 const float* emb,
                 __half* wqt, __half* wkt, __half* wvt,
                 __half* wot, __half* w1t, __half* w2t, __half* embh)
{
    int t = blockIdx.x;
    if (t >= 12288) {
        int i = (t - 12288) * 256 + threadIdx.x;
        int n4 = MK * DIM / 4;
        int stride = 1024 * 256;
        const float4* in = (const float4*)emb;
        __half2* out = (__half2*)embh;
        for (; i < n4; i += stride) {
            float4 v = in[i];
            out[2 * i]     = __floats2half2_rn(v.x, v.y);
            out[2 * i + 1] = __floats2half2_rn(v.z, v.w);
        }
        return;
    }
    __shared__ float tile[32][33];
    const float* in; __half* out; int K, N, lt;
    if (t < 4096) {
        K = DIM; N = DIM; lt = t & 1023;
        int sel = t >> 10;
        in  = sel == 0 ? wq  : sel == 1 ? wk  : sel == 2 ? wv  : wo;
        out = sel == 0 ? wqt : sel == 1 ? wkt : sel == 2 ? wvt : wot;
    } else if (t < 8192) {
        K = DIM; N = HIDDEN; lt = t - 4096; in = w1; out = w1t;
    } else {
        K = HIDDEN; N = DIM; lt = t - 8192; in = w2; out = w2t;
    }
    int tilesX = N >> 5;
    int bx = (lt % tilesX) * 32;
    int by = (lt / tilesX) * 32;
    int tx = threadIdx.x & 31, ty = threadIdx.x >> 5;
    #pragma unroll
    for (int i = 0; i < 32; i += 8)
        tile[ty + i][tx] = in[(size_t)(by + ty + i) * N + bx + tx];
    __syncthreads();
    #pragma unroll
    for (int i = 0; i < 32; i += 8)
        out[(size_t)(bx + ty + i) * K + by + tx] = __float2half_rn(tile[tx][ty + i]);
}

// ==================== LayerNorm (half output) ====================
__global__ __launch_bounds__(256)
void ln_kernel(const float* __restrict__ x, const float* __restrict__ g,
               const float* __restrict__ bt, __half* __restrict__ out)
{
    int row = blockIdx.x;
    int t = threadIdx.x;
    const float4* xr = (const float4*)(x + (size_t)row * DIM);
    float4 v = xr[t];
    float s  = v.x + v.y + v.z + v.w;
    float sq = v.x*v.x + v.y*v.y + v.z*v.z + v.w*v.w;

    #pragma unroll
    for (int off = 16; off; off >>= 1) {
        s  += __shfl_xor_sync(0xffffffffu, s,  off);
        sq += __shfl_xor_sync(0xffffffffu, sq, off);
    }
    __shared__ float ss[8], sqs[8];
    int warp = t >> 5, lane = t & 31;
    if (lane == 0) { ss[warp] = s; sqs[warp] = sq; }
    __syncthreads();
    if (t < 32) {
        float a = (t < 8) ? ss[t]  : 0.f;
        float b = (t < 8) ? sqs[t] : 0.f;
        #pragma unroll
        for (int off = 4; off; off >>= 1) {
            a += __shfl_xor_sync(0xffffffffu, a, off);
            b += __shfl_xor_sync(0xffffffffu, b, off);
        }
        if (t == 0) { ss[0] = a; sqs[0] = b; }
    }
    __syncthreads();
    float mu  = ss[0]  * (1.0f / DIM);
    float var = sqs[0] * (1.0f / DIM) - mu * mu;
    float inv = rsqrtf(var + 1e-5f);

    float4 gv = ((const float4*)g)[t];
    float4 bv = ((const float4*)bt)[t];
    __half2* o2 = (__half2*)(out + (size_t)row * DIM);
    o2[2 * t]     = __floats2half2_rn((v.x - mu) * inv * gv.x + bv.x,
                                      (v.y - mu) * inv * gv.y + bv.y);
    o2[2 * t + 1] = __floats2half2_rn((v.z - mu) * inv * gv.z + bv.z,
                                      (v.w - mu) * inv * gv.w + bv.w);
}

// ==================== split-K reduce: out += p0 + p1 + bias ====================
__global__ __launch_bounds__(256)
void reduce2_kernel(float* __restrict__ out, const float* __restrict__ p0,
                    const float* __restrict__ p1, const float* __restrict__ bias)
{
    int i = blockIdx.x * 256 + threadIdx.x;
    int col4 = (i & (DIM / 4 - 1)) * 4;
    float4 o = ((float4*)out)[i];
    float4 a = ((const float4*)p0)[i];
    float4 b = ((const float4*)p1)[i];
    float4 bb = *(const float4*)(bias + col4);
    o.x += a.x + b.x + bb.x;
    o.y += a.y + b.y + bb.y;
    o.z += a.z + b.z + bb.z;
    o.w += a.w + b.w + bb.w;
    ((float4*)out)[i] = o;
}

// ==================== fp16 GEMM: CTA 128x256, warp 64x64, 1 CTA/SM ===========
#define BM    128
#define BN    256
#define KCH   64
#define SKH   72
#define A_TILE_H (BM * SKH)
#define B_TILE_H (BN * SKH)
#define STAGE_H (A_TILE_H + B_TILE_H)
#define N_STG 3
#define GEMM_SMEM (N_STG * STAGE_H * 2)   // 165888 bytes

__global__ __launch_bounds__(256, 1)
void h16_gemm(int M, int N, int K, int lda, int ldb,
              const __half* __restrict__ A0, const __half* __restrict__ Bt0,
              const float* __restrict__ bias0, const float* __restrict__ res,
              void* __restrict__ C0, int mode,
              const __half* __restrict__ A1, const __half* __restrict__ Bt1,
              const float* __restrict__ bias1, void* __restrict__ C1,
              const __half* __restrict__ A2, const __half* __restrict__ Bt2,
              const float* __restrict__ bias2, void* __restrict__ C2, int rows2)
{
    extern __shared__ __half smh[];

    const __half* A = A0; const __half* Bt = Bt0;
    const float* bias = bias0; void* Cv = C0;
    if (blockIdx.z == 1) { A = A1; Bt = Bt1; bias = bias1; Cv = C1; }
    else if (blockIdx.z == 2) {
        if ((int)blockIdx.y * BM >= rows2) return;
        A = A2; Bt = Bt2; bias = bias2; Cv = C2;
    }

    int tid = threadIdx.x;
    int lane = tid & 31;
    int warp = tid >> 5;
    int warp_m = (warp & 1) * 64;
    int warp_n = (warp >> 1) * 64;
    int r = lane >> 2;
    int c = lane & 3;

    int ctaM = blockIdx.y * BM;
    int ctaN = blockIdx.x * BN;

    const __half* gA = A  + (size_t)ctaM * lda;
    const __half* gB = Bt + (size_t)ctaN * ldb;

    int ldRow = tid >> 3;
    int ldCh  = (tid & 7) * 8;

    const int nk = K / KCH;

    uint32_t smb = (uint32_t)__cvta_generic_to_shared(smh);
    int aRowSel = lane & 15;
    int aKSel   = (lane >> 4) * 8;
    int bNSel   = (lane & 7) + ((lane >> 4) << 3);
    int bKSel   = ((lane >> 3) & 1) * 8;
    uint32_t aBase = smb + (uint32_t)(((warp_m + aRowSel) * SKH + aKSel) * 2);
    uint32_t bBase = smb + (uint32_t)((A_TILE_H + (warp_n + bNSel) * SKH + bKSel) * 2);

    #define ISSUE_STAGE(s, k0)                                                     \
    do {                                                                           \
        __half* sA_ = smh + (s) * STAGE_H;                                         \
        __half* sB_ = sA_ + A_TILE_H;                                              \
        const __half* a_ = gA + (k0);                                              \
        const __half* b_ = gB + (k0);                                              \
        _Pragma("unroll")                                                          \
        for (int j = 0; j < 4; j++) {                                              \
            int row = ldRow + j * 32;                                              \
            cp16(sA_ + (size_t)row * SKH + ldCh, a_ + (size_t)row * lda + ldCh);   \
        }                                                                          \
        _Pragma("unroll")                                                          \
        for (int j = 0; j < 8; j++) {                                              \
            int row = ldRow + j * 32;                                              \
            cp16(sB_ + (size_t)row * SKH + ldCh, b_ + (size_t)row * ldb + ldCh);   \
        }                                                                          \
        asm volatile("cp.async.commit_group;");                                    \
    } while (0)

    ISSUE_STAGE(0, 0);
    if (nk > 1) ISSUE_STAGE(1, KCH);
    else        asm volatile("cp.async.commit_group;");

    float acc[4][8][4] = {};

    for (int kt = 0; kt < nk; kt++) {
        int buf = kt % N_STG;
        if (kt + 1 < nk) asm volatile("cp.async.wait_group 1;");
        else             asm volatile("cp.async.wait_group 0;");
        __syncthreads();

        if (kt + 2 < nk) {
            int s = (kt + 2) % N_STG;
            ISSUE_STAGE(s, (kt + 2) * KCH);
        }

        uint32_t stOff = (uint32_t)(buf * STAGE_H * 2);

        #pragma unroll
        for (int ks = 0; ks < 4; ks++) {
            uint32_t af[4][4], bf[8][2];
            uint32_t kOff = (uint32_t)(ks * 16 * 2);
            #pragma unroll
            for (int mt = 0; mt < 4; mt++)
                ldsm_x4(af[mt][0], af[mt][1], af[mt][2], af[mt][3],
                        aBase + stOff + kOff + (uint32_t)(mt * 16 * SKH * 2));
            #pragma unroll
            for (int np = 0; np < 4; np++)
                ldsm_x4(bf[2 * np][0], bf[2 * np][1], bf[2 * np + 1][0], bf[2 * np + 1][1],
                        bBase + stOff + kOff + (uint32_t)(np * 16 * SKH * 2));
            #pragma unroll
            for (int mt = 0; mt < 4; mt++)
                #pragma unroll
                for (int nt = 0; nt < 8; nt++)
                    mma_f16(acc[mt][nt], af[mt], bf[nt]);
        }
    }
    #undef ISSUE_STAGE

    // ---- epilogue ----
    float*  Cf = (float*)Cv;
    __half* Ch = (__half*)Cv;
    #pragma unroll
    for (int mt = 0; mt < 4; mt++) {
        #pragma unroll
        for (int nt = 0; nt < 8; nt++) {
            int row = ctaM + warp_m + mt * 16 + r;
            int col = ctaN + warp_n + nt * 8 + 2 * c;
            if (mode == 3) {
                *(float2*)(Cf + (size_t)row * N + col) =
                    make_float2(acc[mt][nt][0], acc[mt][nt][1]);
                *(float2*)(Cf + (size_t)(row + 8) * N + col) =
                    make_float2(acc[mt][nt][2], acc[mt][nt][3]);
                continue;
            }
            float b0 = bias[col], b1 = bias[col + 1];
            float v0 = acc[mt][nt][0] + b0;
            float v1 = acc[mt][nt][1] + b1;
            float v2 = acc[mt][nt][2] + b0;
            float v3 = acc[mt][nt][3] + b1;
            if (mode == 2) {
                const float* r0 = res + (size_t)row * N + col;
                const float* r1 = res + (size_t)(row + 8) * N + col;
                v0 += r0[0]; v1 += r0[1];
                v2 += r1[0]; v3 += r1[1];
                *(float2*)(Cf + (size_t)row * N + col)       = make_float2(v0, v1);
                *(float2*)(Cf + (size_t)(row + 8) * N + col) = make_float2(v2, v3);
            } else {
                if (mode == 1) {
                    v0 = gelu_exact(v0); v1 = gelu_exact(v1);
                    v2 = gelu_exact(v2); v3 = gelu_exact(v3);
                }
                *(__half2*)(Ch + (size_t)row * N + col)       = __floats2half2_rn(v0, v1);
                *(__half2*)(Ch + (size_t)(row + 8) * N + col) = __floats2half2_rn(v2, v3);
            }
        }
    }
}

// ==================== fp16 flash attention (register P, no smem round-trip) ==
#define BQ_T   128
#define TILE_K 64
#define SKKH 72
#define SKVH 72
#define NT_KV (NK / TILE_K)
#define ATT_SMEM ((3*TILE_K*SKKH + 3*TILE_K*SKVH) * 2)   // 55296 B

__global__ __launch_bounds__(256, 2)
void attn_mma(const __half* __restrict__ Q, const __half* __restrict__ Kg,
              const __half* __restrict__ Vg, __half* __restrict__ ctx)
{
    extern __shared__ __half smA[];
    __half* KsB = smA;                       // [3][64][SKKH]
    __half* VsB = smA + 3 * TILE_K * SKKH;   // [3][64][SKVH]

    int b = blockIdx.z, h = blockIdx.y, qt = blockIdx.x;
    int tid = threadIdx.x, lane = tid & 31, w = tid >> 5;
    int r = lane >> 2, c = lane & 3;

    const __half* Qb = Q  + ((size_t)(b * NQ + qt * BQ_T)) * DIM + h * HD;
    const __half* Kb = Kg + ((size_t)b * NK) * DIM + h * HD;
    const __half* Vb = Vg + ((size_t)b * NK) * DIM + h * HD;

    #define ATT_ISSUE(s, kt_)                                                      \
    do {                                                                           \
        const __half* kp_ = Kb + (size_t)(kt_) * TILE_K * DIM;                     \
        const __half* vp_ = Vb + (size_t)(kt_) * TILE_K * DIM;                     \
        __half* Kd_ = KsB + (s) * TILE_K * SKKH;                                   \
        __half* Vd_ = VsB + (s) * TILE_K * SKVH;                                   \
        _Pragma("unroll")                                                          \
        for (int i = 0; i < 2; i++) {                                              \
            int idx = tid + i * 256;                                               \
            int row = idx >> 3, ch = (idx & 7) * 8;                                \
            cp16(&Kd_[row * SKKH + ch], kp_ + (size_t)row * DIM + ch);             \
            cp16(&Vd_[row * SKVH + ch], vp_ + (size_t)row * DIM + ch);             \
        }                                                                          \
        asm volatile("cp.async.commit_group;");                                    \
    } while (0)

    ATT_ISSUE(0, 0);
    ATT_ISSUE(1, 1);

    // Q fragments scaled by (1/8)*log2(e) -> scores in log2 domain
    uint32_t qf[4][4];
    {
        const float qs = 0.125f * 1.4426950408889634f;
        const __half2 sc = __floats2half2_rn(qs, qs);
        const __half* q0 = Qb + (size_t)(w * 16 + r) * DIM;
        const __half* q1 = Qb + (size_t)(w * 16 + r + 8) * DIM;
        #pragma unroll
        for (int kg = 0; kg < 4; kg++) {
            __half2 a0 = __hmul2(*(const __half2*)(q0 + kg * 16 + 2 * c), sc);
            __half2 a1 = __hmul2(*(const __half2*)(q1 + kg * 16 + 2 * c), sc);
            __half2 a2 = __hmul2(*(const __half2*)(q0 + kg * 16 + 2 * c + 8), sc);
            __half2 a3 = __hmul2(*(const __half2*)(q1 + kg * 16 + 2 * c + 8), sc);
            qf[kg][0] = *(uint32_t*)&a0; qf[kg][1] = *(uint32_t*)&a1;
            qf[kg][2] = *(uint32_t*)&a2; qf[kg][3] = *(uint32_t*)&a3;
        }
    }

    float m0 = -1e30f, m1 = -1e30f, l0 = 0.f, l1 = 0.f;
    float accO[8][4] = {};
    int l16 = lane & 15, nsel = lane >> 4;

    uint32_t smb = (uint32_t)__cvta_generic_to_shared(smA);
    int bNSel = (lane & 7) + ((lane >> 4) << 3);
    int bKSel = ((lane >> 3) & 1) * 8;
    uint32_t kFragBase = smb + (uint32_t)((bNSel * SKKH + bKSel) * 2);

    for (int kt = 0; kt < NT_KV; kt++) {
        int buf = kt % 3;
        if (kt + 1 < NT_KV) asm volatile("cp.async.wait_group 1;");
        else                asm volatile("cp.async.wait_group 0;");
        __syncthreads();

        if (kt + 2 < NT_KV) ATT_ISSUE((kt + 2) % 3, kt + 2);

        const __half* Vt = VsB + buf * TILE_K * SKVH;
        uint32_t kStage = (uint32_t)(buf * TILE_K * SKKH * 2);

        // S (log2 domain) = Qs @ K^T
        float accS[8][4] = {};
        #pragma unroll
        for (int kg = 0; kg < 4; kg++) {
            uint32_t kOff = (uint32_t)(kg * 16 * 2);
            #pragma unroll
            for (int np = 0; np < 4; np++) {
                uint32_t bf0[2], bf1[2];
                ldsm_x4(bf0[0], bf0[1], bf1[0], bf1[1],
                        kFragBase + kStage + kOff + (uint32_t)(np * 16 * SKKH * 2));
                mma_f16(accS[2 * np],     qf[kg], bf0);
                mma_f16(accS[2 * np + 1], qf[kg], bf1);
            }
        }

        // online softmax (base-2)
        float mx0 = -1e30f, mx1 = -1e30f;
        #pragma unroll
        for (int nt = 0; nt < 8; nt++) {
            mx0 = fmaxf(mx0, fmaxf(accS[nt][0], accS[nt][1]));
            mx1 = fmaxf(mx1, fmaxf(accS[nt][2], accS[nt][3]));
        }
        mx0 = fmaxf(mx0, __shfl_xor_sync(0xffffffffu, mx0, 1));
        mx0 = fmaxf(mx0, __shfl_xor_sync(0xffffffffu, mx0, 2));
        mx1 = fmaxf(mx1, __shfl_xor_sync(0xffffffffu, mx1, 1));
        mx1 = fmaxf(mx1, __shfl_xor_sync(0xffffffffu, mx1, 2));
        float mn0 = fmaxf(m0, mx0), mn1 = fmaxf(m1, mx1);
        float f0 = exp2f(m0 - mn0), f1 = exp2f(m1 - mn1);
        float s0 = 0.f, s1 = 0.f;
        #pragma unroll
        for (int nt = 0; nt < 8; nt++) {
            accS[nt][0] = exp2f(accS[nt][0] - mn0);
            accS[nt][1] = exp2f(accS[nt][1] - mn0);
            accS[nt][2] = exp2f(accS[nt][2] - mn1);
            accS[nt][3] = exp2f(accS[nt][3] - mn1);
            s0 += accS[nt][0] + accS[nt][1];
            s1 += accS[nt][2] + accS[nt][3];
        }
        s0 += __shfl_xor_sync(0xffffffffu, s0, 1);
        s0 += __shfl_xor_sync(0xffffffffu, s0, 2);
        s1 += __shfl_xor_sync(0xffffffffu, s1, 1);
        s1 += __shfl_xor_sync(0xffffffffu, s1, 2);
        l0 = l0 * f0 + s0; l1 = l1 * f1 + s1;
        m0 = mn0; m1 = mn1;
        #pragma unroll
        for (int nt = 0; nt < 8; nt++) {
            accO[nt][0] *= f0; accO[nt][1] *= f0;
            accO[nt][2] *= f1; accO[nt][3] *= f1;
        }

        // O += P @ V : P A-frags built in registers (C-frag == A-frag layout),
        // V via ldmatrix.x4.trans
        #pragma unroll
        for (int kg = 0; kg < 4; kg++) {
            uint32_t af[4];
            af[0] = pack_h2(accS[2 * kg][0],     accS[2 * kg][1]);
            af[1] = pack_h2(accS[2 * kg][2],     accS[2 * kg][3]);
            af[2] = pack_h2(accS[2 * kg + 1][0], accS[2 * kg + 1][1]);
            af[3] = pack_h2(accS[2 * kg + 1][2], accS[2 * kg + 1][3]);
            #pragma unroll
            for (int nt = 0; nt < 8; nt += 2) {
                uint32_t vaddr = (uint32_t)__cvta_generic_to_shared(
                    Vt + (size_t)(kg * 16 + l16) * SKVH + (nt + nsel) * 8);
                uint32_t b0, b1, b2, b3;
                ldsm_x4_trans(b0, b1, b2, b3, vaddr);
                uint32_t bfa[2] = { b0, b1 }, bfb[2] = { b2, b3 };
                mma_f16(accO[nt], af, bfa);
                mma_f16(accO[nt + 1], af, bfb);
            }
        }
    }
    #undef ATT_ISSUE

    float inv0 = 1.f / l0, inv1 = 1.f / l1;
    __half* Cb = ctx + ((size_t)(b * NQ + qt * BQ_T + w * 16)) * DIM + h * HD;
    #pragma unroll
    for (int nt = 0; nt < 8; nt++) {
        *(__half2*)(Cb + (size_t)r * DIM + nt * 8 + 2 * c) =
            __floats2half2_rn(accO[nt][0] * inv0, accO[nt][1] * inv0);
        *(__half2*)(Cb + (size_t)(r + 8) * DIM + nt * 8 + 2 * c) =
            __floats2half2_rn(accO[nt][2] * inv1, accO[nt][3] * inv1);
    }
}

// ==================== launch =================================================
extern "C" void kernel_launch(void* const* d_in, const int* in_sizes, int n_in,
                              void* d_out, int out_size)
{
    const float* tgt  = (const float*)d_in[0];
    const float* emb  = (const float*)d_in[1];
    const float* ln_g = (const float*)d_in[2];
    const float* ln_b = (const float*)d_in[3];
    const float* wq = (const float*)d_in[4];  const float* bq = (const float*)d_in[5];
    const float* wk = (const float*)d_in[6];  const float* bk = (const float*)d_in[7];
    const float* wv = (const float*)d_in[8];  const float* bv = (const float*)d_in[9];
    const float* wo = (const float*)d_in[10]; const float* bo = (const float*)d_in[11];
    const float* w1 = (const float*)d_in[12]; const float* b1 = (const float*)d_in[13];
    const float* w2 = (const float*)d_in[14]; const float* b2 = (const float*)d_in[15];
    float* out = (float*)d_out;

    __half *qn, *q, *k, *v, *ctx, *h1, *embh, *wqt, *wkt, *wvt, *wot, *w1t, *w2t;
    cudaGetSymbolAddress((void**)&qn,   g_qn);
    cudaGetSymbolAddress((void**)&q,    g_q);
    cudaGetSymbolAddress((void**)&k,    g_k);
    cudaGetSymbolAddress((void**)&v,    g_v);
    cudaGetSymbolAddress((void**)&ctx,  g_ctx);
    cudaGetSymbolAddress((void**)&h1,   g_h1);
    cudaGetSymbolAddress((void**)&embh, g_embh);
    cudaGetSymbolAddress((void**)&wqt,  g_wqt);
    cudaGetSymbolAddress((void**)&wkt,  g_wkt);
    cudaGetSymbolAddress((void**)&wvt,  g_wvt);
    cudaGetSymbolAddress((void**)&wot,  g_wot);
    cudaGetSymbolAddress((void**)&w1t,  g_w1t);
    cudaGetSymbolAddress((void**)&w2t,  g_w2t);

    float* p0 = (float*)k;
    float* p1 = (float*)v;

    cudaFuncSetAttribute(h16_gemm, cudaFuncAttributeMaxDynamicSharedMemorySize, GEMM_SMEM);
    cudaFuncSetAttribute(attn_mma, cudaFuncAttributeMaxDynamicSharedMemorySize, ATT_SMEM);

    // 0) prep: 6 transposes + emb conversion
    prep_kernel<<<13312, 256>>>(wq, wk, wv, wo, w1, w2, emb,
                                wqt, wkt, wvt, wot, w1t, w2t, embh);

    // 1) qn = LN(tgt)
    ln_kernel<<<MQ, 256>>>(tgt, ln_g, ln_b, qn);

    // 2-4) K,V,Q fused: z=0 K, z=1 V, z=2 Q (Q only y<32)
    h16_gemm<<<dim3(DIM / BN, MK / BM, 3), 256, GEMM_SMEM>>>(
        MK, DIM, DIM, DIM, DIM,
        embh, wkt, bk, nullptr, (void*)k, 0,
        embh, wvt, bv, (void*)v,
        qn,   wqt, bq, (void*)q, MQ);

    // 5) ctx = softmax(Q K^T / 8) V
    attn_mma<<<dim3(NQ / BQ_T, HEADS, BSZ), 256, ATT_SMEM>>>(q, k, v, ctx);

    // 6) tgt1 = tgt + ctx @ wo + bo -> d_out
    h16_gemm<<<dim3(DIM / BN, MQ / BM, 1), 256, GEMM_SMEM>>>(
        MQ, DIM, DIM, DIM, DIM,
        ctx, wot, bo, tgt, (void*)out, 2,
        ctx, wot, bo, (void*)out,
        ctx, wot, bo, (void*)out, MQ);

    // 7) h_in = LN(tgt1)
    ln_kernel<<<MQ, 256>>>(out, ln_g, ln_b, qn);

    // 8) h1 = gelu(h_in @ w1 + b1)
    h16_gemm<<<dim3(HIDDEN / BN, MQ / BM, 1), 256, GEMM_SMEM>>>(
        MQ, HIDDEN, DIM, DIM, DIM,
        qn, w1t, b1, nullptr, (void*)h1, 1,
        qn, w1t, b1, (void*)h1,
        qn, w1t, b1, (void*)h1, MQ);

    // 9a) MLP2 split-K=2 partials
    h16_gemm<<<dim3(DIM / BN, MQ / BM, 2), 256, GEMM_SMEM>>>(
        MQ, DIM, HIDDEN / 2, HIDDEN, HIDDEN,
        h1, w2t, b2, nullptr, (void*)p0, 3,
        h1 + HIDDEN / 2, w2t + HIDDEN / 2, b2, (void*)p1,
        h1, w2t, b2, (void*)p0, MQ);

    // 9b) out += p0 + p1 + b2
    reduce2_kernel<<<MQ * DIM / 4 / 256, 256>>>(out, p0, p1, b2);
}

// round 14
// speedup vs baseline: 1.0700x; 1.0406x over previous
#include <cuda_runtime.h>
#include <cuda_fp16.h>
#include <math.h>
#include <stdint.h>

// ---------------- problem constants ----------------
#define BSZ     4
#define NQ      1024
#define NK      2048
#define DIM     1024
#define HEADS   16
#define HD      64
#define HIDDEN  4096
#define MQ      (BSZ*NQ)   // 4096
#define MK      (BSZ*NK)   // 8192

// ---------------- scratch ----------
__device__ __align__(128) __half g_qn  [(size_t)MQ * DIM];
__device__ __align__(128) __half g_q   [(size_t)MQ * DIM];
__device__ __align__(128) __half g_k   [(size_t)MK * DIM];   // reused as fp32 p0 after attn
__device__ __align__(128) __half g_v   [(size_t)MK * DIM];   // reused as fp32 p1 after attn
__device__ __align__(128) __half g_ctx [(size_t)MQ * DIM];
__device__ __align__(128) __half g_h1  [(size_t)MQ * HIDDEN];
__device__ __align__(128) __half g_embh[(size_t)MK * DIM];
__device__ __align__(128) __half g_wqt [(size_t)DIM * DIM];
__device__ __align__(128) __half g_wkt [(size_t)DIM * DIM];
__device__ __align__(128) __half g_wvt [(size_t)DIM * DIM];
__device__ __align__(128) __half g_wot [(size_t)DIM * DIM];
__device__ __align__(128) __half g_w1t [(size_t)DIM * HIDDEN];
__device__ __align__(128) __half g_w2t [(size_t)HIDDEN * DIM];

// ==================== helpers ====================
__device__ __forceinline__ float gelu_exact(float x) {
    return 0.5f * x * (1.0f + erff(x * 0.70710678118654752f));
}
__device__ __forceinline__ void cp16(void* s, const void* g) {
    uint32_t sa = (uint32_t)__cvta_generic_to_shared(s);
    asm volatile("cp.async.ca.shared.global [%0], [%1], 16;" :: "r"(sa), "l"(g));
}
__device__ __forceinline__ void mma_f16(float d[4], const uint32_t a[4], const uint32_t b[2]) {
    asm volatile(
        "mma.sync.aligned.m16n8k16.row.col.f32.f16.f16.f32 "
        "{%0,%1,%2,%3}, {%4,%5,%6,%7}, {%8,%9}, {%0,%1,%2,%3};"
        : "+f"(d[0]), "+f"(d[1]), "+f"(d[2]), "+f"(d[3])
        : "r"(a[0]), "r"(a[1]), "r"(a[2]), "r"(a[3]), "r"(b[0]), "r"(b[1]));
}
__device__ __forceinline__ void ldsm_x4(uint32_t& d0, uint32_t& d1,
                                        uint32_t& d2, uint32_t& d3, uint32_t addr) {
    asm volatile("ldmatrix.sync.aligned.m8n8.x4.shared.b16 {%0,%1,%2,%3}, [%4];"
                 : "=r"(d0), "=r"(d1), "=r"(d2), "=r"(d3) : "r"(addr));
}
__device__ __forceinline__ void ldsm_x4_trans(uint32_t& d0, uint32_t& d1,
                                              uint32_t& d2, uint32_t& d3, uint32_t addr) {
    asm volatile("ldmatrix.sync.aligned.m8n8.x4.trans.shared.b16 {%0,%1,%2,%3}, [%4];"
                 : "=r"(d0), "=r"(d1), "=r"(d2), "=r"(d3) : "r"(addr));
}
__device__ __forceinline__ uint32_t pack_h2(float a, float b) {
    __half2 h = __floats2half2_rn(a, b);
    return *(uint32_t*)&h;
}

// ==================== prep: 6 weight transposes + emb conversion =============
__global__ __launch_bounds__(256)
void prep_kernel(const float* wq, const float* wk, const float* wv,
                 const float* wo, const float* w1, const float* w2,
                 const float* emb,
                 __half* wqt, __half* wkt, __half* wvt,
                 __half* wot, __half* w1t, __half* w2t, __half* embh)
{
    int t = blockIdx.x;
    if (t >= 12288) {
        int i = (t - 12288) * 256 + threadIdx.x;
        int n4 = MK * DIM / 4;
        int stride = 1024 * 256;
        const float4* in = (const float4*)emb;
        __half2* out = (__half2*)embh;
        for (; i < n4; i += stride) {
            float4 v = in[i];
            out[2 * i]     = __floats2half2_rn(v.x, v.y);
            out[2 * i + 1] = __floats2half2_rn(v.z, v.w);
        }
        return;
    }
    __shared__ float tile[32][33];
    const float* in; __half* out; int K, N, lt;
    if (t < 4096) {
        K = DIM; N = DIM; lt = t & 1023;
        int sel = t >> 10;
        in  = sel == 0 ? wq  : sel == 1 ? wk  : sel == 2 ? wv  : wo;
        out = sel == 0 ? wqt : sel == 1 ? wkt : sel == 2 ? wvt : wot;
    } else if (t < 8192) {
        K = DIM; N = HIDDEN; lt = t - 4096; in = w1; out = w1t;
    } else {
        K = HIDDEN; N = DIM; lt = t - 8192; in = w2; out = w2t;
    }
    int tilesX = N >> 5;
    int bx = (lt % tilesX) * 32;
    int by = (lt / tilesX) * 32;
    int tx = threadIdx.x & 31, ty = threadIdx.x >> 5;
    #pragma unroll
    for (int i = 0; i < 32; i += 8)
        tile[ty + i][tx] = in[(size_t)(by + ty + i) * N + bx + tx];
    __syncthreads();
    #pragma unroll
    for (int i = 0; i < 32; i += 8)
        out[(size_t)(bx + ty + i) * K + by + tx] = __float2half_rn(tile[tx][ty + i]);
}

// ==================== LayerNorm (half output) ====================
__global__ __launch_bounds__(256)
void ln_kernel(const float* __restrict__ x, const float* __restrict__ g,
               const float* __restrict__ bt, __half* __restrict__ out)
{
    int row = blockIdx.x;
    int t = threadIdx.x;
    const float4* xr = (const float4*)(x + (size_t)row * DIM);
    float4 v = xr[t];
    float s  = v.x + v.y + v.z + v.w;
    float sq = v.x*v.x + v.y*v.y + v.z*v.z + v.w*v.w;

    #pragma unroll
    for (int off = 16; off; off >>= 1) {
        s  += __shfl_xor_sync(0xffffffffu, s,  off);
        sq += __shfl_xor_sync(0xffffffffu, sq, off);
    }
    __shared__ float ss[8], sqs[8];
    int warp = t >> 5, lane = t & 31;
    if (lane == 0) { ss[warp] = s; sqs[warp] = sq; }
    __syncthreads();
    if (t < 32) {
        float a = (t < 8) ? ss[t]  : 0.f;
        float b = (t < 8) ? sqs[t] : 0.f;
        #pragma unroll
        for (int off = 4; off; off >>= 1) {
            a += __shfl_xor_sync(0xffffffffu, a, off);
            b += __shfl_xor_sync(0xffffffffu, b, off);
        }
        if (t == 0) { ss[0] = a; sqs[0] = b; }
    }
    __syncthreads();
    float mu  = ss[0]  * (1.0f / DIM);
    float var = sqs[0] * (1.0f / DIM) - mu * mu;
    float inv = rsqrtf(var + 1e-5f);

    float4 gv = ((const float4*)g)[t];
    float4 bv = ((const float4*)bt)[t];
    __half2* o2 = (__half2*)(out + (size_t)row * DIM);
    o2[2 * t]     = __floats2half2_rn((v.x - mu) * inv * gv.x + bv.x,
                                      (v.y - mu) * inv * gv.y + bv.y);
    o2[2 * t + 1] = __floats2half2_rn((v.z - mu) * inv * gv.z + bv.z,
                                      (v.w - mu) * inv * gv.w + bv.w);
}

// ==================== split-K reduce: out += p0 + p1 + bias ====================
__global__ __launch_bounds__(256)
void reduce2_kernel(float* __restrict__ out, const float* __restrict__ p0,
                    const float* __restrict__ p1, const float* __restrict__ bias)
{
    int i = blockIdx.x * 256 + threadIdx.x;
    int col4 = (i & (DIM / 4 - 1)) * 4;
    float4 o = ((float4*)out)[i];
    float4 a = ((const float4*)p0)[i];
    float4 b = ((const float4*)p1)[i];
    float4 bb = *(const float4*)(bias + col4);
    o.x += a.x + b.x + bb.x;
    o.y += a.y + b.y + bb.y;
    o.z += a.z + b.z + bb.z;
    o.w += a.w + b.w + bb.w;
    ((float4*)out)[i] = o;
}

// ==================== fp16 GEMM: CTA 128x256, warp 64x64, 1 CTA/SM ===========
#define BM    128
#define BN    256
#define KCH   64
#define SKH   72
#define A_TILE_H (BM * SKH)
#define B_TILE_H (BN * SKH)
#define STAGE_H (A_TILE_H + B_TILE_H)
#define N_STG 3
#define GEMM_SMEM (N_STG * STAGE_H * 2)   // 165888 bytes

__global__ __launch_bounds__(256, 1)
void h16_gemm(int M, int N, int K, int lda, int ldb,
              const __half* __restrict__ A0, const __half* __restrict__ Bt0,
              const float* __restrict__ bias0, const float* __restrict__ res,
              void* __restrict__ C0, int mode,
              const __half* __restrict__ A1, const __half* __restrict__ Bt1,
              const float* __restrict__ bias1, void* __restrict__ C1,
              const __half* __restrict__ A2, const __half* __restrict__ Bt2,
              const float* __restrict__ bias2, void* __restrict__ C2, int rows2)
{
    extern __shared__ __half smh[];

    const __half* A = A0; const __half* Bt = Bt0;
    const float* bias = bias0; void* Cv = C0;
    if (blockIdx.z == 1) { A = A1; Bt = Bt1; bias = bias1; Cv = C1; }
    else if (blockIdx.z == 2) {
        if ((int)blockIdx.y * BM >= rows2) return;
        A = A2; Bt = Bt2; bias = bias2; Cv = C2;
    }

    int tid = threadIdx.x;
    int lane = tid & 31;
    int warp = tid >> 5;
    int warp_m = (warp & 1) * 64;
    int warp_n = (warp >> 1) * 64;
    int r = lane >> 2;
    int c = lane & 3;

    int ctaM = blockIdx.y * BM;
    int ctaN = blockIdx.x * BN;

    const __half* gA = A  + (size_t)ctaM * lda;
    const __half* gB = Bt + (size_t)ctaN * ldb;

    int ldRow = tid >> 3;
    int ldCh  = (tid & 7) * 8;

    const int nk = K / KCH;

    uint32_t smb = (uint32_t)__cvta_generic_to_shared(smh);
    int aRowSel = lane & 15;
    int aKSel   = (lane >> 4) * 8;
    int bNSel   = (lane & 7) + ((lane >> 4) << 3);
    int bKSel   = ((lane >> 3) & 1) * 8;
    uint32_t aBase = smb + (uint32_t)(((warp_m + aRowSel) * SKH + aKSel) * 2);
    uint32_t bBase = smb + (uint32_t)((A_TILE_H + (warp_n + bNSel) * SKH + bKSel) * 2);

    #define ISSUE_STAGE(s, k0)                                                     \
    do {                                                                           \
        __half* sA_ = smh + (s) * STAGE_H;                                         \
        __half* sB_ = sA_ + A_TILE_H;                                              \
        const __half* a_ = gA + (k0);                                              \
        const __half* b_ = gB + (k0);                                              \
        _Pragma("unroll")                                                          \
        for (int j = 0; j < 4; j++) {                                              \
            int row = ldRow + j * 32;                                              \
            cp16(sA_ + (size_t)row * SKH + ldCh, a_ + (size_t)row * lda + ldCh);   \
        }                                                                          \
        _Pragma("unroll")                                                          \
        for (int j = 0; j < 8; j++) {                                              \
            int row = ldRow + j * 32;                                              \
            cp16(sB_ + (size_t)row * SKH + ldCh, b_ + (size_t)row * ldb + ldCh);   \
        }                                                                          \
        asm volatile("cp.async.commit_group;");                                    \
    } while (0)

    ISSUE_STAGE(0, 0);
    if (nk > 1) ISSUE_STAGE(1, KCH);
    else        asm volatile("cp.async.commit_group;");

    float acc[4][8][4] = {};

    for (int kt = 0; kt < nk; kt++) {
        int buf = kt % N_STG;
        if (kt + 1 < nk) asm volatile("cp.async.wait_group 1;");
        else             asm volatile("cp.async.wait_group 0;");
        __syncthreads();

        if (kt + 2 < nk) {
            int s = (kt + 2) % N_STG;
            ISSUE_STAGE(s, (kt + 2) * KCH);
        }

        uint32_t stOff = (uint32_t)(buf * STAGE_H * 2);

        #pragma unroll
        for (int ks = 0; ks < 4; ks++) {
            uint32_t af[4][4], bf[8][2];
            uint32_t kOff = (uint32_t)(ks * 16 * 2);
            #pragma unroll
            for (int mt = 0; mt < 4; mt++)
                ldsm_x4(af[mt][0], af[mt][1], af[mt][2], af[mt][3],
                        aBase + stOff + kOff + (uint32_t)(mt * 16 * SKH * 2));
            #pragma unroll
            for (int np = 0; np < 4; np++)
                ldsm_x4(bf[2 * np][0], bf[2 * np][1], bf[2 * np + 1][0], bf[2 * np + 1][1],
                        bBase + stOff + kOff + (uint32_t)(np * 16 * SKH * 2));
            #pragma unroll
            for (int mt = 0; mt < 4; mt++)
                #pragma unroll
                for (int nt = 0; nt < 8; nt++)
                    mma_f16(acc[mt][nt], af[mt], bf[nt]);
        }
    }
    #undef ISSUE_STAGE

    // ---- epilogue ----
    float*  Cf = (float*)Cv;
    __half* Ch = (__half*)Cv;
    #pragma unroll
    for (int mt = 0; mt < 4; mt++) {
        #pragma unroll
        for (int nt = 0; nt < 8; nt++) {
            int row = ctaM + warp_m + mt * 16 + r;
            int col = ctaN + warp_n + nt * 8 + 2 * c;
            if (mode == 3) {
                *(float2*)(Cf + (size_t)row * N + col) =
                    make_float2(acc[mt][nt][0], acc[mt][nt][1]);
                *(float2*)(Cf + (size_t)(row + 8) * N + col) =
                    make_float2(acc[mt][nt][2], acc[mt][nt][3]);
                continue;
            }
            float b0 = bias[col], b1 = bias[col + 1];
            float v0 = acc[mt][nt][0] + b0;
            float v1 = acc[mt][nt][1] + b1;
            float v2 = acc[mt][nt][2] + b0;
            float v3 = acc[mt][nt][3] + b1;
            if (mode == 2) {
                const float* r0 = res + (size_t)row * N + col;
                const float* r1 = res + (size_t)(row + 8) * N + col;
                v0 += r0[0]; v1 += r0[1];
                v2 += r1[0]; v3 += r1[1];
                *(float2*)(Cf + (size_t)row * N + col)       = make_float2(v0, v1);
                *(float2*)(Cf + (size_t)(row + 8) * N + col) = make_float2(v2, v3);
            } else {
                if (mode == 1) {
                    v0 = gelu_exact(v0); v1 = gelu_exact(v1);
                    v2 = gelu_exact(v2); v3 = gelu_exact(v3);
                }
                *(__half2*)(Ch + (size_t)row * N + col)       = __floats2half2_rn(v0, v1);
                *(__half2*)(Ch + (size_t)(row + 8) * N + col) = __floats2half2_rn(v2, v3);
            }
        }
    }
}

// ==================== fp16 flash attention v3 =================================
// CTA = 256 q-rows, 8 warps x 32q. No max-tracking (scores bounded; exact
// softmax identity). Register P. 3-stage K/V cp.async.
#define BQ_T   256
#define TILE_K 64
#define SKKH 72
#define SKVH 72
#define NT_KV (NK / TILE_K)
#define ATT_SMEM ((3*TILE_K*SKKH + 3*TILE_K*SKVH) * 2)   // 55296 B

__global__ __launch_bounds__(256, 1)
void attn_mma(const __half* __restrict__ Q, const __half* __restrict__ Kg,
              const __half* __restrict__ Vg, __half* __restrict__ ctx)
{
    extern __shared__ __half smA[];
    __half* KsB = smA;                       // [3][64][SKKH]
    __half* VsB = smA + 3 * TILE_K * SKKH;   // [3][64][SKVH]

    int b = blockIdx.z, h = blockIdx.y, qt = blockIdx.x;
    int tid = threadIdx.x, lane = tid & 31, w = tid >> 5;
    int r = lane >> 2, c = lane & 3;

    const __half* Qb = Q  + ((size_t)(b * NQ + qt * BQ_T)) * DIM + h * HD;
    const __half* Kb = Kg + ((size_t)b * NK) * DIM + h * HD;
    const __half* Vb = Vg + ((size_t)b * NK) * DIM + h * HD;

    #define ATT_ISSUE(s, kt_)                                                      \
    do {                                                                           \
        const __half* kp_ = Kb + (size_t)(kt_) * TILE_K * DIM;                     \
        const __half* vp_ = Vb + (size_t)(kt_) * TILE_K * DIM;                     \
        __half* Kd_ = KsB + (s) * TILE_K * SKKH;                                   \
        __half* Vd_ = VsB + (s) * TILE_K * SKVH;                                   \
        _Pragma("unroll")                                                          \
        for (int i = 0; i < 2; i++) {                                              \
            int idx = tid + i * 256;                                               \
            int row = idx >> 3, ch = (idx & 7) * 8;                                \
            cp16(&Kd_[row * SKKH + ch], kp_ + (size_t)row * DIM + ch);             \
            cp16(&Vd_[row * SKVH + ch], vp_ + (size_t)row * DIM + ch);             \
        }                                                                          \
        asm volatile("cp.async.commit_group;");                                    \
    } while (0)

    ATT_ISSUE(0, 0);
    ATT_ISSUE(1, 1);

    // Q fragments for two 16-row blocks, scaled by (1/8)*log2(e)
    uint32_t qf0[4][4], qf1[4][4];
    {
        const float qs = 0.125f * 1.4426950408889634f;
        const __half2 sc = __floats2half2_rn(qs, qs);
        #pragma unroll
        for (int blk = 0; blk < 2; blk++) {
            const __half* q0 = Qb + (size_t)(w * 32 + blk * 16 + r) * DIM;
            const __half* q1 = q0 + 8 * DIM;
            #pragma unroll
            for (int kg = 0; kg < 4; kg++) {
                __half2 a0 = __hmul2(*(const __half2*)(q0 + kg * 16 + 2 * c), sc);
                __half2 a1 = __hmul2(*(const __half2*)(q1 + kg * 16 + 2 * c), sc);
                __half2 a2 = __hmul2(*(const __half2*)(q0 + kg * 16 + 2 * c + 8), sc);
                __half2 a3 = __hmul2(*(const __half2*)(q1 + kg * 16 + 2 * c + 8), sc);
                uint32_t* dst = blk ? qf1[kg] : qf0[kg];
                dst[0] = *(uint32_t*)&a0; dst[1] = *(uint32_t*)&a1;
                dst[2] = *(uint32_t*)&a2; dst[3] = *(uint32_t*)&a3;
            }
        }
    }

    float lA0 = 0.f, lA1 = 0.f, lB0 = 0.f, lB1 = 0.f;
    float accO0[8][4] = {}, accO1[8][4] = {};
    int l16 = lane & 15, nsel = lane >> 4;

    uint32_t smb = (uint32_t)__cvta_generic_to_shared(smA);
    int bNSel = (lane & 7) + ((lane >> 4) << 3);
    int bKSel = ((lane >> 3) & 1) * 8;
    uint32_t kFragBase = smb + (uint32_t)((bNSel * SKKH + bKSel) * 2);

    for (int kt = 0; kt < NT_KV; kt++) {
        int buf = kt % 3;
        if (kt + 1 < NT_KV) asm volatile("cp.async.wait_group 1;");
        else                asm volatile("cp.async.wait_group 0;");
        __syncthreads();

        if (kt + 2 < NT_KV) ATT_ISSUE((kt + 2) % 3, kt + 2);

        const __half* Vt = VsB + buf * TILE_K * SKVH;
        uint32_t kStage = (uint32_t)(buf * TILE_K * SKKH * 2);

        // S = Qs @ K^T for both 16-row blocks (shared K fragments)
        float accS0[8][4] = {}, accS1[8][4] = {};
        #pragma unroll
        for (int kg = 0; kg < 4; kg++) {
            uint32_t kOff = (uint32_t)(kg * 16 * 2);
            #pragma unroll
            for (int np = 0; np < 4; np++) {
                uint32_t bf0[2], bf1[2];
                ldsm_x4(bf0[0], bf0[1], bf1[0], bf1[1],
                        kFragBase + kStage + kOff + (uint32_t)(np * 16 * SKKH * 2));
                mma_f16(accS0[2 * np],     qf0[kg], bf0);
                mma_f16(accS0[2 * np + 1], qf0[kg], bf1);
                mma_f16(accS1[2 * np],     qf1[kg], bf0);
                mma_f16(accS1[2 * np + 1], qf1[kg], bf1);
            }
        }

        // exp2 (no max subtraction; scores bounded) + row sums
        float sA0 = 0.f, sA1 = 0.f, sB0 = 0.f, sB1 = 0.f;
        #pragma unroll
        for (int nt = 0; nt < 8; nt++) {
            accS0[nt][0] = exp2f(accS0[nt][0]);
            accS0[nt][1] = exp2f(accS0[nt][1]);
            accS0[nt][2] = exp2f(accS0[nt][2]);
            accS0[nt][3] = exp2f(accS0[nt][3]);
            sA0 += accS0[nt][0] + accS0[nt][1];
            sA1 += accS0[nt][2] + accS0[nt][3];
            accS1[nt][0] = exp2f(accS1[nt][0]);
            accS1[nt][1] = exp2f(accS1[nt][1]);
            accS1[nt][2] = exp2f(accS1[nt][2]);
            accS1[nt][3] = exp2f(accS1[nt][3]);
            sB0 += accS1[nt][0] + accS1[nt][1];
            sB1 += accS1[nt][2] + accS1[nt][3];
        }
        sA0 += __shfl_xor_sync(0xffffffffu, sA0, 1);
        sA0 += __shfl_xor_sync(0xffffffffu, sA0, 2);
        sA1 += __shfl_xor_sync(0xffffffffu, sA1, 1);
        sA1 += __shfl_xor_sync(0xffffffffu, sA1, 2);
        sB0 += __shfl_xor_sync(0xffffffffu, sB0, 1);
        sB0 += __shfl_xor_sync(0xffffffffu, sB0, 2);
        sB1 += __shfl_xor_sync(0xffffffffu, sB1, 1);
        sB1 += __shfl_xor_sync(0xffffffffu, sB1, 2);
        lA0 += sA0; lA1 += sA1; lB0 += sB0; lB1 += sB1;

        // O += P @ V (register P, shared V fragments)
        #pragma unroll
        for (int kg = 0; kg < 4; kg++) {
            uint32_t af0[4], af1[4];
            af0[0] = pack_h2(accS0[2 * kg][0],     accS0[2 * kg][1]);
            af0[1] = pack_h2(accS0[2 * kg][2],     accS0[2 * kg][3]);
            af0[2] = pack_h2(accS0[2 * kg + 1][0], accS0[2 * kg + 1][1]);
            af0[3] = pack_h2(accS0[2 * kg + 1][2], accS0[2 * kg + 1][3]);
            af1[0] = pack_h2(accS1[2 * kg][0],     accS1[2 * kg][1]);
            af1[1] = pack_h2(accS1[2 * kg][2],     accS1[2 * kg][3]);
            af1[2] = pack_h2(accS1[2 * kg + 1][0], accS1[2 * kg + 1][1]);
            af1[3] = pack_h2(accS1[2 * kg + 1][2], accS1[2 * kg + 1][3]);
            #pragma unroll
            for (int nt = 0; nt < 8; nt += 2) {
                uint32_t vaddr = (uint32_t)__cvta_generic_to_shared(
                    Vt + (size_t)(kg * 16 + l16) * SKVH + (nt + nsel) * 8);
                uint32_t b0, b1, b2, b3;
                ldsm_x4_trans(b0, b1, b2, b3, vaddr);
                uint32_t bfa[2] = { b0, b1 }, bfb[2] = { b2, b3 };
                mma_f16(accO0[nt], af0, bfa);
                mma_f16(accO0[nt + 1], af0, bfb);
                mma_f16(accO1[nt], af1, bfa);
                mma_f16(accO1[nt + 1], af1, bfb);
            }
        }
    }
    #undef ATT_ISSUE

    float iA0 = 1.f / lA0, iA1 = 1.f / lA1, iB0 = 1.f / lB0, iB1 = 1.f / lB1;
    __half* Cb0 = ctx + ((size_t)(b * NQ + qt * BQ_T + w * 32)) * DIM + h * HD;
    __half* Cb1 = Cb0 + 16 * DIM;
    #pragma unroll
    for (int nt = 0; nt < 8; nt++) {
        *(__half2*)(Cb0 + (size_t)r * DIM + nt * 8 + 2 * c) =
            __floats2half2_rn(accO0[nt][0] * iA0, accO0[nt][1] * iA0);
        *(__half2*)(Cb0 + (size_t)(r + 8) * DIM + nt * 8 + 2 * c) =
            __floats2half2_rn(accO0[nt][2] * iA1, accO0[nt][3] * iA1);
        *(__half2*)(Cb1 + (size_t)r * DIM + nt * 8 + 2 * c) =
            __floats2half2_rn(accO1[nt][0] * iB0, accO1[nt][1] * iB0);
        *(__half2*)(Cb1 + (size_t)(r + 8) * DIM + nt * 8 + 2 * c) =
            __floats2half2_rn(accO1[nt][2] * iB1, accO1[nt][3] * iB1);
    }
}

// ==================== launch =================================================
extern "C" void kernel_launch(void* const* d_in, const int* in_sizes, int n_in,
                              void* d_out, int out_size)
{
    const float* tgt  = (const float*)d_in[0];
    const float* emb  = (const float*)d_in[1];
    const float* ln_g = (const float*)d_in[2];
    const float* ln_b = (const float*)d_in[3];
    const float* wq = (const float*)d_in[4];  const float* bq = (const float*)d_in[5];
    const float* wk = (const float*)d_in[6];  const float* bk = (const float*)d_in[7];
    const float* wv = (const float*)d_in[8];  const float* bv = (const float*)d_in[9];
    const float* wo = (const float*)d_in[10]; const float* bo = (const float*)d_in[11];
    const float* w1 = (const float*)d_in[12]; const float* b1 = (const float*)d_in[13];
    const float* w2 = (const float*)d_in[14]; const float* b2 = (const float*)d_in[15];
    float* out = (float*)d_out;

    __half *qn, *q, *k, *v, *ctx, *h1, *embh, *wqt, *wkt, *wvt, *wot, *w1t, *w2t;
    cudaGetSymbolAddress((void**)&qn,   g_qn);
    cudaGetSymbolAddress((void**)&q,    g_q);
    cudaGetSymbolAddress((void**)&k,    g_k);
    cudaGetSymbolAddress((void**)&v,    g_v);
    cudaGetSymbolAddress((void**)&ctx,  g_ctx);
    cudaGetSymbolAddress((void**)&h1,   g_h1);
    cudaGetSymbolAddress((void**)&embh, g_embh);
    cudaGetSymbolAddress((void**)&wqt,  g_wqt);
    cudaGetSymbolAddress((void**)&wkt,  g_wkt);
    cudaGetSymbolAddress((void**)&wvt,  g_wvt);
    cudaGetSymbolAddress((void**)&wot,  g_wot);
    cudaGetSymbolAddress((void**)&w1t,  g_w1t);
    cudaGetSymbolAddress((void**)&w2t,  g_w2t);

    float* p0 = (float*)k;
    float* p1 = (float*)v;

    cudaFuncSetAttribute(h16_gemm, cudaFuncAttributeMaxDynamicSharedMemorySize, GEMM_SMEM);
    cudaFuncSetAttribute(attn_mma, cudaFuncAttributeMaxDynamicSharedMemorySize, ATT_SMEM);

    // 0) prep
    prep_kernel<<<13312, 256>>>(wq, wk, wv, wo, w1, w2, emb,
                                wqt, wkt, wvt, wot, w1t, w2t, embh);

    // 1) qn = LN(tgt)
    ln_kernel<<<MQ, 256>>>(tgt, ln_g, ln_b, qn);

    // 2-4) K,V,Q fused
    h16_gemm<<<dim3(DIM / BN, MK / BM, 3), 256, GEMM_SMEM>>>(
        MK, DIM, DIM, DIM, DIM,
        embh, wkt, bk, nullptr, (void*)k, 0,
        embh, wvt, bv, (void*)v,
        qn,   wqt, bq, (void*)q, MQ);

    // 5) ctx = softmax(Q K^T / 8) V
    attn_mma<<<dim3(NQ / BQ_T, HEADS, BSZ), 256, ATT_SMEM>>>(q, k, v, ctx);

    // 6) tgt1 = tgt + ctx @ wo + bo -> d_out
    h16_gemm<<<dim3(DIM / BN, MQ / BM, 1), 256, GEMM_SMEM>>>(
        MQ, DIM, DIM, DIM, DIM,
        ctx, wot, bo, tgt, (void*)out, 2,
        ctx, wot, bo, (void*)out,
        ctx, wot, bo, (void*)out, MQ);

    // 7) h_in = LN(tgt1)
    ln_kernel<<<MQ, 256>>>(out, ln_g, ln_b, qn);

    // 8) h1 = gelu(h_in @ w1 + b1)
    h16_gemm<<<dim3(HIDDEN / BN, MQ / BM, 1), 256, GEMM_SMEM>>>(
        MQ, HIDDEN, DIM, DIM, DIM,
        qn, w1t, b1, nullptr, (void*)h1, 1,
        qn, w1t, b1, (void*)h1,
        qn, w1t, b1, (void*)h1, MQ);

    // 9a) MLP2 split-K=2 partials
    h16_gemm<<<dim3(DIM / BN, MQ / BM, 2), 256, GEMM_SMEM>>>(
        MQ, DIM, HIDDEN / 2, HIDDEN, HIDDEN,
        h1, w2t, b2, nullptr, (void*)p0, 3,
        h1 + HIDDEN / 2, w2t + HIDDEN / 2, b2, (void*)p1,
        h1, w2t, b2, (void*)p0, MQ);

    // 9b) out += p0 + p1 + b2
    reduce2_kernel<<<MQ * DIM / 4 / 256, 256>>>(out, p0, p1, b2);
}

// round 15
// speedup vs baseline: 1.0934x; 1.0219x over previous
#include <cuda_runtime.h>
#include <cuda_fp16.h>
#include <math.h>
#include <stdint.h>

// ---------------- problem constants ----------------
#define BSZ     4
#define NQ      1024
#define NK      2048
#define DIM     1024
#define HEADS   16
#define HD      64
#define HIDDEN  4096
#define MQ      (BSZ*NQ)   // 4096
#define MK      (BSZ*NK)   // 8192

// ---------------- scratch ----------
__device__ __align__(128) __half g_qn  [(size_t)MQ * DIM];
__device__ __align__(128) __half g_q   [(size_t)MQ * DIM];
__device__ __align__(128) __half g_k   [(size_t)MK * DIM];   // reused as fp32 p0 after attn
__device__ __align__(128) __half g_v   [(size_t)MK * DIM];   // reused as fp32 p1 after attn
__device__ __align__(128) __half g_ctx [(size_t)MQ * DIM];
__device__ __align__(128) __half g_h1  [(size_t)MQ * HIDDEN];
__device__ __align__(128) __half g_embh[(size_t)MK * DIM];
__device__ __align__(128) __half g_wqt [(size_t)DIM * DIM];
__device__ __align__(128) __half g_wkt [(size_t)DIM * DIM];
__device__ __align__(128) __half g_wvt [(size_t)DIM * DIM];
__device__ __align__(128) __half g_wot [(size_t)DIM * DIM];
__device__ __align__(128) __half g_w1t [(size_t)DIM * HIDDEN];
__device__ __align__(128) __half g_w2t [(size_t)HIDDEN * DIM];

// ==================== helpers ====================
__device__ __forceinline__ float gelu_exact(float x) {
    return 0.5f * x * (1.0f + erff(x * 0.70710678118654752f));
}
__device__ __forceinline__ void cp16(void* s, const void* g) {
    uint32_t sa = (uint32_t)__cvta_generic_to_shared(s);
    asm volatile("cp.async.ca.shared.global [%0], [%1], 16;" :: "r"(sa), "l"(g));
}
__device__ __forceinline__ void mma_f16(float d[4], const uint32_t a[4], const uint32_t b[2]) {
    asm volatile(
        "mma.sync.aligned.m16n8k16.row.col.f32.f16.f16.f32 "
        "{%0,%1,%2,%3}, {%4,%5,%6,%7}, {%8,%9}, {%0,%1,%2,%3};"
        : "+f"(d[0]), "+f"(d[1]), "+f"(d[2]), "+f"(d[3])
        : "r"(a[0]), "r"(a[1]), "r"(a[2]), "r"(a[3]), "r"(b[0]), "r"(b[1]));
}
__device__ __forceinline__ void ldsm_x4(uint32_t& d0, uint32_t& d1,
                                        uint32_t& d2, uint32_t& d3, uint32_t addr) {
    asm volatile("ldmatrix.sync.aligned.m8n8.x4.shared.b16 {%0,%1,%2,%3}, [%4];"
                 : "=r"(d0), "=r"(d1), "=r"(d2), "=r"(d3) : "r"(addr));
}
__device__ __forceinline__ void ldsm_x4_trans(uint32_t& d0, uint32_t& d1,
                                              uint32_t& d2, uint32_t& d3, uint32_t addr) {
    asm volatile("ldmatrix.sync.aligned.m8n8.x4.trans.shared.b16 {%0,%1,%2,%3}, [%4];"
                 : "=r"(d0), "=r"(d1), "=r"(d2), "=r"(d3) : "r"(addr));
}
__device__ __forceinline__ uint32_t pack_h2(float a, float b) {
    __half2 h = __floats2half2_rn(a, b);
    return *(uint32_t*)&h;
}
__device__ __forceinline__ uint32_t ex2_h2(uint32_t x) {
    uint32_t r;
    asm("ex2.approx.f16x2 %0, %1;" : "=r"(r) : "r"(x));
    return r;
}

// ==================== prep: 6 weight transposes + emb conversion =============
__global__ __launch_bounds__(256)
void prep_kernel(const float* wq, const float* wk, const float* wv,
                 const float* wo, const float* w1, const float* w2,
                 const float* emb,
                 __half* wqt, __half* wkt, __half* wvt,
                 __half* wot, __half* w1t, __half* w2t, __half* embh)
{
    int t = blockIdx.x;
    if (t >= 12288) {
        int i = (t - 12288) * 256 + threadIdx.x;
        int n4 = MK * DIM / 4;
        int stride = 1024 * 256;
        const float4* in = (const float4*)emb;
        __half2* out = (__half2*)embh;
        for (; i < n4; i += stride) {
            float4 v = in[i];
            out[2 * i]     = __floats2half2_rn(v.x, v.y);
            out[2 * i + 1] = __floats2half2_rn(v.z, v.w);
        }
        return;
    }
    __shared__ float tile[32][33];
    const float* in; __half* out; int K, N, lt;
    if (t < 4096) {
        K = DIM; N = DIM; lt = t & 1023;
        int sel = t >> 10;
        in  = sel == 0 ? wq  : sel == 1 ? wk  : sel == 2 ? wv  : wo;
        out = sel == 0 ? wqt : sel == 1 ? wkt : sel == 2 ? wvt : wot;
    } else if (t < 8192) {
        K = DIM; N = HIDDEN; lt = t - 4096; in = w1; out = w1t;
    } else {
        K = HIDDEN; N = DIM; lt = t - 8192; in = w2; out = w2t;
    }
    int tilesX = N >> 5;
    int bx = (lt % tilesX) * 32;
    int by = (lt / tilesX) * 32;
    int tx = threadIdx.x & 31, ty = threadIdx.x >> 5;
    #pragma unroll
    for (int i = 0; i < 32; i += 8)
        tile[ty + i][tx] = in[(size_t)(by + ty + i) * N + bx + tx];
    __syncthreads();
    #pragma unroll
    for (int i = 0; i < 32; i += 8)
        out[(size_t)(bx + ty + i) * K + by + tx] = __float2half_rn(tile[tx][ty + i]);
}

// ==================== LayerNorm (half output) ====================
__global__ __launch_bounds__(256)
void ln_kernel(const float* __restrict__ x, const float* __restrict__ g,
               const float* __restrict__ bt, __half* __restrict__ out)
{
    int row = blockIdx.x;
    int t = threadIdx.x;
    const float4* xr = (const float4*)(x + (size_t)row * DIM);
    float4 v = xr[t];
    float s  = v.x + v.y + v.z + v.w;
    float sq = v.x*v.x + v.y*v.y + v.z*v.z + v.w*v.w;

    #pragma unroll
    for (int off = 16; off; off >>= 1) {
        s  += __shfl_xor_sync(0xffffffffu, s,  off);
        sq += __shfl_xor_sync(0xffffffffu, sq, off);
    }
    __shared__ float ss[8], sqs[8];
    int warp = t >> 5, lane = t & 31;
    if (lane == 0) { ss[warp] = s; sqs[warp] = sq; }
    __syncthreads();
    if (t < 32) {
        float a = (t < 8) ? ss[t]  : 0.f;
        float b = (t < 8) ? sqs[t] : 0.f;
        #pragma unroll
        for (int off = 4; off; off >>= 1) {
            a += __shfl_xor_sync(0xffffffffu, a, off);
            b += __shfl_xor_sync(0xffffffffu, b, off);
        }
        if (t == 0) { ss[0] = a; sqs[0] = b; }
    }
    __syncthreads();
    float mu  = ss[0]  * (1.0f / DIM);
    float var = sqs[0] * (1.0f / DIM) - mu * mu;
    float inv = rsqrtf(var + 1e-5f);

    float4 gv = ((const float4*)g)[t];
    float4 bv = ((const float4*)bt)[t];
    __half2* o2 = (__half2*)(out + (size_t)row * DIM);
    o2[2 * t]     = __floats2half2_rn((v.x - mu) * inv * gv.x + bv.x,
                                      (v.y - mu) * inv * gv.y + bv.y);
    o2[2 * t + 1] = __floats2half2_rn((v.z - mu) * inv * gv.z + bv.z,
                                      (v.w - mu) * inv * gv.w + bv.w);
}

// ==================== split-K reduce: out += p0 + p1 + bias ====================
__global__ __launch_bounds__(256)
void reduce2_kernel(float* __restrict__ out, const float* __restrict__ p0,
                    const float* __restrict__ p1, const float* __restrict__ bias)
{
    int i = blockIdx.x * 256 + threadIdx.x;
    int col4 = (i & (DIM / 4 - 1)) * 4;
    float4 o = ((float4*)out)[i];
    float4 a = ((const float4*)p0)[i];
    float4 b = ((const float4*)p1)[i];
    float4 bb = *(const float4*)(bias + col4);
    o.x += a.x + b.x + bb.x;
    o.y += a.y + b.y + bb.y;
    o.z += a.z + b.z + bb.z;
    o.w += a.w + b.w + bb.w;
    ((float4*)out)[i] = o;
}

// ==================== fp16 GEMM: CTA 128x256, warp 64x64, 1 CTA/SM ===========
#define BM    128
#define BN    256
#define KCH   64
#define SKH   72
#define A_TILE_H (BM * SKH)
#define B_TILE_H (BN * SKH)
#define STAGE_H (A_TILE_H + B_TILE_H)
#define N_STG 3
#define GEMM_SMEM (N_STG * STAGE_H * 2)   // 165888 bytes

__global__ __launch_bounds__(256, 1)
void h16_gemm(int M, int N, int K, int lda, int ldb,
              const __half* __restrict__ A0, const __half* __restrict__ Bt0,
              const float* __restrict__ bias0, const float* __restrict__ res,
              void* __restrict__ C0, int mode,
              const __half* __restrict__ A1, const __half* __restrict__ Bt1,
              const float* __restrict__ bias1, void* __restrict__ C1,
              const __half* __restrict__ A2, const __half* __restrict__ Bt2,
              const float* __restrict__ bias2, void* __restrict__ C2, int rows2)
{
    extern __shared__ __half smh[];

    const __half* A = A0; const __half* Bt = Bt0;
    const float* bias = bias0; void* Cv = C0;
    if (blockIdx.z == 1) { A = A1; Bt = Bt1; bias = bias1; Cv = C1; }
    else if (blockIdx.z == 2) {
        if ((int)blockIdx.y * BM >= rows2) return;
        A = A2; Bt = Bt2; bias = bias2; Cv = C2;
    }

    int tid = threadIdx.x;
    int lane = tid & 31;
    int warp = tid >> 5;
    int warp_m = (warp & 1) * 64;
    int warp_n = (warp >> 1) * 64;
    int r = lane >> 2;
    int c = lane & 3;

    int ctaM = blockIdx.y * BM;
    int ctaN = blockIdx.x * BN;

    const __half* gA = A  + (size_t)ctaM * lda;
    const __half* gB = Bt + (size_t)ctaN * ldb;

    int ldRow = tid >> 3;
    int ldCh  = (tid & 7) * 8;

    const int nk = K / KCH;

    uint32_t smb = (uint32_t)__cvta_generic_to_shared(smh);
    int aRowSel = lane & 15;
    int aKSel   = (lane >> 4) * 8;
    int bNSel   = (lane & 7) + ((lane >> 4) << 3);
    int bKSel   = ((lane >> 3) & 1) * 8;
    uint32_t aBase = smb + (uint32_t)(((warp_m + aRowSel) * SKH + aKSel) * 2);
    uint32_t bBase = smb + (uint32_t)((A_TILE_H + (warp_n + bNSel) * SKH + bKSel) * 2);

    #define ISSUE_STAGE(s, k0)                                                     \
    do {                                                                           \
        __half* sA_ = smh + (s) * STAGE_H;                                         \
        __half* sB_ = sA_ + A_TILE_H;                                              \
        const __half* a_ = gA + (k0);                                              \
        const __half* b_ = gB + (k0);                                              \
        _Pragma("unroll")                                                          \
        for (int j = 0; j < 4; j++) {                                              \
            int row = ldRow + j * 32;                                              \
            cp16(sA_ + (size_t)row * SKH + ldCh, a_ + (size_t)row * lda + ldCh);   \
        }                                                                          \
        _Pragma("unroll")                                                          \
        for (int j = 0; j < 8; j++) {                                              \
            int row = ldRow + j * 32;                                              \
            cp16(sB_ + (size_t)row * SKH + ldCh, b_ + (size_t)row * ldb + ldCh);   \
        }                                                                          \
        asm volatile("cp.async.commit_group;");                                    \
    } while (0)

    ISSUE_STAGE(0, 0);
    if (nk > 1) ISSUE_STAGE(1, KCH);
    else        asm volatile("cp.async.commit_group;");

    float acc[4][8][4] = {};

    for (int kt = 0; kt < nk; kt++) {
        int buf = kt % N_STG;
        if (kt + 1 < nk) asm volatile("cp.async.wait_group 1;");
        else             asm volatile("cp.async.wait_group 0;");
        __syncthreads();

        if (kt + 2 < nk) {
            int s = (kt + 2) % N_STG;
            ISSUE_STAGE(s, (kt + 2) * KCH);
        }

        uint32_t stOff = (uint32_t)(buf * STAGE_H * 2);

        #pragma unroll
        for (int ks = 0; ks < 4; ks++) {
            uint32_t af[4][4], bf[8][2];
            uint32_t kOff = (uint32_t)(ks * 16 * 2);
            #pragma unroll
            for (int mt = 0; mt < 4; mt++)
                ldsm_x4(af[mt][0], af[mt][1], af[mt][2], af[mt][3],
                        aBase + stOff + kOff + (uint32_t)(mt * 16 * SKH * 2));
            #pragma unroll
            for (int np = 0; np < 4; np++)
                ldsm_x4(bf[2 * np][0], bf[2 * np][1], bf[2 * np + 1][0], bf[2 * np + 1][1],
                        bBase + stOff + kOff + (uint32_t)(np * 16 * SKH * 2));
            #pragma unroll
            for (int mt = 0; mt < 4; mt++)
                #pragma unroll
                for (int nt = 0; nt < 8; nt++)
                    mma_f16(acc[mt][nt], af[mt], bf[nt]);
        }
    }
    #undef ISSUE_STAGE

    // ---- epilogue ----
    float*  Cf = (float*)Cv;
    __half* Ch = (__half*)Cv;
    #pragma unroll
    for (int mt = 0; mt < 4; mt++) {
        #pragma unroll
        for (int nt = 0; nt < 8; nt++) {
            int row = ctaM + warp_m + mt * 16 + r;
            int col = ctaN + warp_n + nt * 8 + 2 * c;
            if (mode == 3) {
                *(float2*)(Cf + (size_t)row * N + col) =
                    make_float2(acc[mt][nt][0], acc[mt][nt][1]);
                *(float2*)(Cf + (size_t)(row + 8) * N + col) =
                    make_float2(acc[mt][nt][2], acc[mt][nt][3]);
                continue;
            }
            float b0 = bias[col], b1 = bias[col + 1];
            float v0 = acc[mt][nt][0] + b0;
            float v1 = acc[mt][nt][1] + b1;
            float v2 = acc[mt][nt][2] + b0;
            float v3 = acc[mt][nt][3] + b1;
            if (mode == 2) {
                const float* r0 = res + (size_t)row * N + col;
                const float* r1 = res + (size_t)(row + 8) * N + col;
                v0 += r0[0]; v1 += r0[1];
                v2 += r1[0]; v3 += r1[1];
                *(float2*)(Cf + (size_t)row * N + col)       = make_float2(v0, v1);
                *(float2*)(Cf + (size_t)(row + 8) * N + col) = make_float2(v2, v3);
            } else {
                if (mode == 1) {
                    v0 = gelu_exact(v0); v1 = gelu_exact(v1);
                    v2 = gelu_exact(v2); v3 = gelu_exact(v3);
                }
                *(__half2*)(Ch + (size_t)row * N + col)       = __floats2half2_rn(v0, v1);
                *(__half2*)(Ch + (size_t)(row + 8) * N + col) = __floats2half2_rn(v2, v3);
            }
        }
    }
}

// ==================== fp16 flash attention v4 =================================
// CTA = 256 q-rows, 8 warps x 32q. No max-tracking. P = ex2.approx.f16x2 of
// packed scores (half MUFU work). Row sums l = P @ ones via MMA (fp32 acc,
// accumulated across all tiles; zero shuffles). Register P, 3-stage K/V.
#define BQ_T   256
#define TILE_K 64
#define SKKH 72
#define SKVH 72
#define NT_KV (NK / TILE_K)
#define ATT_SMEM ((3*TILE_K*SKKH + 3*TILE_K*SKVH) * 2)   // 55296 B

__global__ __launch_bounds__(256, 1)
void attn_mma(const __half* __restrict__ Q, const __half* __restrict__ Kg,
              const __half* __restrict__ Vg, __half* __restrict__ ctx)
{
    extern __shared__ __half smA[];
    __half* KsB = smA;
    __half* VsB = smA + 3 * TILE_K * SKKH;

    int b = blockIdx.z, h = blockIdx.y, qt = blockIdx.x;
    int tid = threadIdx.x, lane = tid & 31, w = tid >> 5;
    int r = lane >> 2, c = lane & 3;

    const __half* Qb = Q  + ((size_t)(b * NQ + qt * BQ_T)) * DIM + h * HD;
    const __half* Kb = Kg + ((size_t)b * NK) * DIM + h * HD;
    const __half* Vb = Vg + ((size_t)b * NK) * DIM + h * HD;

    #define ATT_ISSUE(s, kt_)                                                      \
    do {                                                                           \
        const __half* kp_ = Kb + (size_t)(kt_) * TILE_K * DIM;                     \
        const __half* vp_ = Vb + (size_t)(kt_) * TILE_K * DIM;                     \
        __half* Kd_ = KsB + (s) * TILE_K * SKKH;                                   \
        __half* Vd_ = VsB + (s) * TILE_K * SKVH;                                   \
        _Pragma("unroll")                                                          \
        for (int i = 0; i < 2; i++) {                                              \
            int idx = tid + i * 256;                                               \
            int row = idx >> 3, ch = (idx & 7) * 8;                                \
            cp16(&Kd_[row * SKKH + ch], kp_ + (size_t)row * DIM + ch);             \
            cp16(&Vd_[row * SKVH + ch], vp_ + (size_t)row * DIM + ch);             \
        }                                                                          \
        asm volatile("cp.async.commit_group;");                                    \
    } while (0)

    ATT_ISSUE(0, 0);
    ATT_ISSUE(1, 1);

    // Q fragments for two 16-row blocks, scaled by (1/8)*log2(e)
    uint32_t qf0[4][4], qf1[4][4];
    {
        const float qs = 0.125f * 1.4426950408889634f;
        const __half2 sc = __floats2half2_rn(qs, qs);
        #pragma unroll
        for (int blk = 0; blk < 2; blk++) {
            const __half* q0 = Qb + (size_t)(w * 32 + blk * 16 + r) * DIM;
            const __half* q1 = q0 + 8 * DIM;
            #pragma unroll
            for (int kg = 0; kg < 4; kg++) {
                __half2 a0 = __hmul2(*(const __half2*)(q0 + kg * 16 + 2 * c), sc);
                __half2 a1 = __hmul2(*(const __half2*)(q1 + kg * 16 + 2 * c), sc);
                __half2 a2 = __hmul2(*(const __half2*)(q0 + kg * 16 + 2 * c + 8), sc);
                __half2 a3 = __hmul2(*(const __half2*)(q1 + kg * 16 + 2 * c + 8), sc);
                uint32_t* dst = blk ? qf1[kg] : qf0[kg];
                dst[0] = *(uint32_t*)&a0; dst[1] = *(uint32_t*)&a1;
                dst[2] = *(uint32_t*)&a2; dst[3] = *(uint32_t*)&a3;
            }
        }
    }

    float lSum0[4] = {}, lSum1[4] = {};   // row sums via ones-MMA (fp32 acc)
    const uint32_t bOnes[2] = { 0x3C003C00u, 0x3C003C00u };
    float accO0[8][4] = {}, accO1[8][4] = {};
    int l16 = lane & 15, nsel = lane >> 4;

    uint32_t smb = (uint32_t)__cvta_generic_to_shared(smA);
    int bNSel = (lane & 7) + ((lane >> 4) << 3);
    int bKSel = ((lane >> 3) & 1) * 8;
    uint32_t kFragBase = smb + (uint32_t)((bNSel * SKKH + bKSel) * 2);

    for (int kt = 0; kt < NT_KV; kt++) {
        int buf = kt % 3;
        if (kt + 1 < NT_KV) asm volatile("cp.async.wait_group 1;");
        else                asm volatile("cp.async.wait_group 0;");
        __syncthreads();

        if (kt + 2 < NT_KV) ATT_ISSUE((kt + 2) % 3, kt + 2);

        const __half* Vt = VsB + buf * TILE_K * SKVH;
        uint32_t kStage = (uint32_t)(buf * TILE_K * SKKH * 2);

        // S = Qs @ K^T for both 16-row blocks (shared K fragments)
        float accS0[8][4] = {}, accS1[8][4] = {};
        #pragma unroll
        for (int kg = 0; kg < 4; kg++) {
            uint32_t kOff = (uint32_t)(kg * 16 * 2);
            #pragma unroll
            for (int np = 0; np < 4; np++) {
                uint32_t bf0[2], bf1[2];
                ldsm_x4(bf0[0], bf0[1], bf1[0], bf1[1],
                        kFragBase + kStage + kOff + (uint32_t)(np * 16 * SKKH * 2));
                mma_f16(accS0[2 * np],     qf0[kg], bf0);
                mma_f16(accS0[2 * np + 1], qf0[kg], bf1);
                mma_f16(accS1[2 * np],     qf1[kg], bf0);
                mma_f16(accS1[2 * np + 1], qf1[kg], bf1);
            }
        }

        // P = exp2(S) directly in fp16 (pack then f16x2 EX2)
        uint32_t pe0a[8], pe0b[8], pe1a[8], pe1b[8];
        #pragma unroll
        for (int nt = 0; nt < 8; nt++) {
            pe0a[nt] = ex2_h2(pack_h2(accS0[nt][0], accS0[nt][1]));
            pe0b[nt] = ex2_h2(pack_h2(accS0[nt][2], accS0[nt][3]));
            pe1a[nt] = ex2_h2(pack_h2(accS1[nt][0], accS1[nt][1]));
            pe1b[nt] = ex2_h2(pack_h2(accS1[nt][2], accS1[nt][3]));
        }

        // O += P @ V ; l += P @ 1 (shared V fragments)
        #pragma unroll
        for (int kg = 0; kg < 4; kg++) {
            uint32_t af0[4], af1[4];
            af0[0] = pe0a[2 * kg];     af0[1] = pe0b[2 * kg];
            af0[2] = pe0a[2 * kg + 1]; af0[3] = pe0b[2 * kg + 1];
            af1[0] = pe1a[2 * kg];     af1[1] = pe1b[2 * kg];
            af1[2] = pe1a[2 * kg + 1]; af1[3] = pe1b[2 * kg + 1];
            mma_f16(lSum0, af0, bOnes);
            mma_f16(lSum1, af1, bOnes);
            #pragma unroll
            for (int nt = 0; nt < 8; nt += 2) {
                uint32_t vaddr = (uint32_t)__cvta_generic_to_shared(
                    Vt + (size_t)(kg * 16 + l16) * SKVH + (nt + nsel) * 8);
                uint32_t b0, b1, b2, b3;
                ldsm_x4_trans(b0, b1, b2, b3, vaddr);
                uint32_t bfa[2] = { b0, b1 }, bfb[2] = { b2, b3 };
                mma_f16(accO0[nt], af0, bfa);
                mma_f16(accO0[nt + 1], af0, bfb);
                mma_f16(accO1[nt], af1, bfa);
                mma_f16(accO1[nt + 1], af1, bfb);
            }
        }
    }
    #undef ATT_ISSUE

    // lSum[0] = sum for row r, lSum[2] = row r+8 (all columns identical)
    float iA0 = 1.f / lSum0[0], iA1 = 1.f / lSum0[2];
    float iB0 = 1.f / lSum1[0], iB1 = 1.f / lSum1[2];
    __half* Cb0 = ctx + ((size_t)(b * NQ + qt * BQ_T + w * 32)) * DIM + h * HD;
    __half* Cb1 = Cb0 + 16 * DIM;
    #pragma unroll
    for (int nt = 0; nt < 8; nt++) {
        *(__half2*)(Cb0 + (size_t)r * DIM + nt * 8 + 2 * c) =
            __floats2half2_rn(accO0[nt][0] * iA0, accO0[nt][1] * iA0);
        *(__half2*)(Cb0 + (size_t)(r + 8) * DIM + nt * 8 + 2 * c) =
            __floats2half2_rn(accO0[nt][2] * iA1, accO0[nt][3] * iA1);
        *(__half2*)(Cb1 + (size_t)r * DIM + nt * 8 + 2 * c) =
            __floats2half2_rn(accO1[nt][0] * iB0, accO1[nt][1] * iB0);
        *(__half2*)(Cb1 + (size_t)(r + 8) * DIM + nt * 8 + 2 * c) =
            __floats2half2_rn(accO1[nt][2] * iB1, accO1[nt][3] * iB1);
    }
}

// ==================== launch =================================================
extern "C" void kernel_launch(void* const* d_in, const int* in_sizes, int n_in,
                              void* d_out, int out_size)
{
    const float* tgt  = (const float*)d_in[0];
    const float* emb  = (const float*)d_in[1];
    const float* ln_g = (const float*)d_in[2];
    const float* ln_b = (const float*)d_in[3];
    const float* wq = (const float*)d_in[4];  const float* bq = (const float*)d_in[5];
    const float* wk = (const float*)d_in[6];  const float* bk = (const float*)d_in[7];
    const float* wv = (const float*)d_in[8];  const float* bv = (const float*)d_in[9];
    const float* wo = (const float*)d_in[10]; const float* bo = (const float*)d_in[11];
    const float* w1 = (const float*)d_in[12]; const float* b1 = (const float*)d_in[13];
    const float* w2 = (const float*)d_in[14]; const float* b2 = (const float*)d_in[15];
    float* out = (float*)d_out;

    __half *qn, *q, *k, *v, *ctx, *h1, *embh, *wqt, *wkt, *wvt, *wot, *w1t, *w2t;
    cudaGetSymbolAddress((void**)&qn,   g_qn);
    cudaGetSymbolAddress((void**)&q,    g_q);
    cudaGetSymbolAddress((void**)&k,    g_k);
    cudaGetSymbolAddress((void**)&v,    g_v);
    cudaGetSymbolAddress((void**)&ctx,  g_ctx);
    cudaGetSymbolAddress((void**)&h1,   g_h1);
    cudaGetSymbolAddress((void**)&embh, g_embh);
    cudaGetSymbolAddress((void**)&wqt,  g_wqt);
    cudaGetSymbolAddress((void**)&wkt,  g_wkt);
    cudaGetSymbolAddress((void**)&wvt,  g_wvt);
    cudaGetSymbolAddress((void**)&wot,  g_wot);
    cudaGetSymbolAddress((void**)&w1t,  g_w1t);
    cudaGetSymbolAddress((void**)&w2t,  g_w2t);

    float* p0 = (float*)k;
    float* p1 = (float*)v;

    cudaFuncSetAttribute(h16_gemm, cudaFuncAttributeMaxDynamicSharedMemorySize, GEMM_SMEM);
    cudaFuncSetAttribute(attn_mma, cudaFuncAttributeMaxDynamicSharedMemorySize, ATT_SMEM);

    // 0) prep
    prep_kernel<<<13312, 256>>>(wq, wk, wv, wo, w1, w2, emb,
                                wqt, wkt, wvt, wot, w1t, w2t, embh);

    // 1) qn = LN(tgt)
    ln_kernel<<<MQ, 256>>>(tgt, ln_g, ln_b, qn);

    // 2-4) K,V,Q fused
    h16_gemm<<<dim3(DIM / BN, MK / BM, 3), 256, GEMM_SMEM>>>(
        MK, DIM, DIM, DIM, DIM,
        embh, wkt, bk, nullptr, (void*)k, 0,
        embh, wvt, bv, (void*)v,
        qn,   wqt, bq, (void*)q, MQ);

    // 5) ctx = softmax(Q K^T / 8) V
    attn_mma<<<dim3(NQ / BQ_T, HEADS, BSZ), 256, ATT_SMEM>>>(q, k, v, ctx);

    // 6) tgt1 = tgt + ctx @ wo + bo -> d_out
    h16_gemm<<<dim3(DIM / BN, MQ / BM, 1), 256, GEMM_SMEM>>>(
        MQ, DIM, DIM, DIM, DIM,
        ctx, wot, bo, tgt, (void*)out, 2,
        ctx, wot, bo, (void*)out,
        ctx, wot, bo, (void*)out, MQ);

    // 7) h_in = LN(tgt1)
    ln_kernel<<<MQ, 256>>>(out, ln_g, ln_b, qn);

    // 8) h1 = gelu(h_in @ w1 + b1)
    h16_gemm<<<dim3(HIDDEN / BN, MQ / BM, 1), 256, GEMM_SMEM>>>(
        MQ, HIDDEN, DIM, DIM, DIM,
        qn, w1t, b1, nullptr, (void*)h1, 1,
        qn, w1t, b1, (void*)h1,
        qn, w1t, b1, (void*)h1, MQ);

    // 9a) MLP2 split-K=2 partials
    h16_gemm<<<dim3(DIM / BN, MQ / BM, 2), 256, GEMM_SMEM>>>(
        MQ, DIM, HIDDEN / 2, HIDDEN, HIDDEN,
        h1, w2t, b2, nullptr, (void*)p0, 3,
        h1 + HIDDEN / 2, w2t + HIDDEN / 2, b2, (void*)p1,
        h1, w2t, b2, (void*)p0, MQ);

    // 9b) out += p0 + p1 + b2
    reduce2_kernel<<<MQ * DIM / 4 / 256, 256>>>(out, p0, p1, b2);
}

// round 16
// speedup vs baseline: 1.1029x; 1.0087x over previous
#include <cuda_runtime.h>
#include <cuda_fp16.h>
#include <math.h>
#include <stdint.h>

// ---------------- problem constants ----------------
#define BSZ     4
#define NQ      1024
#define NK      2048
#define DIM     1024
#define HEADS   16
#define HD      64
#define HIDDEN  4096
#define MQ      (BSZ*NQ)   // 4096
#define MK      (BSZ*NK)   // 8192

// ---------------- scratch ----------
__device__ __align__(128) __half g_qn  [(size_t)MQ * DIM];
__device__ __align__(128) __half g_q   [(size_t)MQ * DIM];
__device__ __align__(128) __half g_k   [(size_t)MK * DIM];
__device__ __align__(128) __half g_v   [(size_t)MK * DIM];
__device__ __align__(128) __half g_ctx [(size_t)MQ * DIM];
__device__ __align__(128) __half g_h1  [(size_t)MQ * HIDDEN];
__device__ __align__(128) __half g_embh[(size_t)MK * DIM];
__device__ __align__(128) __half g_wqt [(size_t)DIM * DIM];
__device__ __align__(128) __half g_wkt [(size_t)DIM * DIM];
__device__ __align__(128) __half g_wvt [(size_t)DIM * DIM];
__device__ __align__(128) __half g_wot [(size_t)DIM * DIM];
__device__ __align__(128) __half g_w1t [(size_t)DIM * HIDDEN];
__device__ __align__(128) __half g_w2t [(size_t)HIDDEN * DIM];

// ==================== helpers ====================
__device__ __forceinline__ float gelu_exact(float x) {
    return 0.5f * x * (1.0f + erff(x * 0.70710678118654752f));
}
__device__ __forceinline__ void cp16(void* s, const void* g) {
    uint32_t sa = (uint32_t)__cvta_generic_to_shared(s);
    asm volatile("cp.async.ca.shared.global [%0], [%1], 16;" :: "r"(sa), "l"(g));
}
__device__ __forceinline__ void mma_f16(float d[4], const uint32_t a[4], const uint32_t b[2]) {
    asm volatile(
        "mma.sync.aligned.m16n8k16.row.col.f32.f16.f16.f32 "
        "{%0,%1,%2,%3}, {%4,%5,%6,%7}, {%8,%9}, {%0,%1,%2,%3};"
        : "+f"(d[0]), "+f"(d[1]), "+f"(d[2]), "+f"(d[3])
        : "r"(a[0]), "r"(a[1]), "r"(a[2]), "r"(a[3]), "r"(b[0]), "r"(b[1]));
}
__device__ __forceinline__ void ldsm_x4(uint32_t& d0, uint32_t& d1,
                                        uint32_t& d2, uint32_t& d3, uint32_t addr) {
    asm volatile("ldmatrix.sync.aligned.m8n8.x4.shared.b16 {%0,%1,%2,%3}, [%4];"
                 : "=r"(d0), "=r"(d1), "=r"(d2), "=r"(d3) : "r"(addr));
}
__device__ __forceinline__ void ldsm_x4_trans(uint32_t& d0, uint32_t& d1,
                                              uint32_t& d2, uint32_t& d3, uint32_t addr) {
    asm volatile("ldmatrix.sync.aligned.m8n8.x4.trans.shared.b16 {%0,%1,%2,%3}, [%4];"
                 : "=r"(d0), "=r"(d1), "=r"(d2), "=r"(d3) : "r"(addr));
}
__device__ __forceinline__ uint32_t pack_h2(float a, float b) {
    __half2 h = __floats2half2_rn(a, b);
    return *(uint32_t*)&h;
}
__device__ __forceinline__ uint32_t ex2_h2(uint32_t x) {
    uint32_t r;
    asm("ex2.approx.f16x2 %0, %1;" : "=r"(r) : "r"(x));
    return r;
}

// ==================== prep: 6 weight transposes + emb conversion =============
__global__ __launch_bounds__(256)
void prep_kernel(const float* wq, const float* wk, const float* wv,
                 const float* wo, const float* w1, const float* w2,
                 const float* emb,
                 __half* wqt, __half* wkt, __half* wvt,
                 __half* wot, __half* w1t, __half* w2t, __half* embh)
{
    int t = blockIdx.x;
    if (t >= 12288) {
        int i = (t - 12288) * 256 + threadIdx.x;
        int n4 = MK * DIM / 4;
        int stride = 1024 * 256;
        const float4* in = (const float4*)emb;
        __half2* out = (__half2*)embh;
        for (; i < n4; i += stride) {
            float4 v = in[i];
            out[2 * i]     = __floats2half2_rn(v.x, v.y);
            out[2 * i + 1] = __floats2half2_rn(v.z, v.w);
        }
        return;
    }
    __shared__ float tile[32][33];
    const float* in; __half* out; int K, N, lt;
    if (t < 4096) {
        K = DIM; N = DIM; lt = t & 1023;
        int sel = t >> 10;
        in  = sel == 0 ? wq  : sel == 1 ? wk  : sel == 2 ? wv  : wo;
        out = sel == 0 ? wqt : sel == 1 ? wkt : sel == 2 ? wvt : wot;
    } else if (t < 8192) {
        K = DIM; N = HIDDEN; lt = t - 4096; in = w1; out = w1t;
    } else {
        K = HIDDEN; N = DIM; lt = t - 8192; in = w2; out = w2t;
    }
    int tilesX = N >> 5;
    int bx = (lt % tilesX) * 32;
    int by = (lt / tilesX) * 32;
    int tx = threadIdx.x & 31, ty = threadIdx.x >> 5;
    #pragma unroll
    for (int i = 0; i < 32; i += 8)
        tile[ty + i][tx] = in[(size_t)(by + ty + i) * N + bx + tx];
    __syncthreads();
    #pragma unroll
    for (int i = 0; i < 32; i += 8)
        out[(size_t)(bx + ty + i) * K + by + tx] = __float2half_rn(tile[tx][ty + i]);
}

// ==================== LayerNorm (half output) ====================
__global__ __launch_bounds__(256)
void ln_kernel(const float* __restrict__ x, const float* __restrict__ g,
               const float* __restrict__ bt, __half* __restrict__ out)
{
    int row = blockIdx.x;
    int t = threadIdx.x;
    const float4* xr = (const float4*)(x + (size_t)row * DIM);
    float4 v = xr[t];
    float s  = v.x + v.y + v.z + v.w;
    float sq = v.x*v.x + v.y*v.y + v.z*v.z + v.w*v.w;

    #pragma unroll
    for (int off = 16; off; off >>= 1) {
        s  += __shfl_xor_sync(0xffffffffu, s,  off);
        sq += __shfl_xor_sync(0xffffffffu, sq, off);
    }
    __shared__ float ss[8], sqs[8];
    int warp = t >> 5, lane = t & 31;
    if (lane == 0) { ss[warp] = s; sqs[warp] = sq; }
    __syncthreads();
    if (t < 32) {
        float a = (t < 8) ? ss[t]  : 0.f;
        float b = (t < 8) ? sqs[t] : 0.f;
        #pragma unroll
        for (int off = 4; off; off >>= 1) {
            a += __shfl_xor_sync(0xffffffffu, a, off);
            b += __shfl_xor_sync(0xffffffffu, b, off);
        }
        if (t == 0) { ss[0] = a; sqs[0] = b; }
    }
    __syncthreads();
    float mu  = ss[0]  * (1.0f / DIM);
    float var = sqs[0] * (1.0f / DIM) - mu * mu;
    float inv = rsqrtf(var + 1e-5f);

    float4 gv = ((const float4*)g)[t];
    float4 bv = ((const float4*)bt)[t];
    __half2* o2 = (__half2*)(out + (size_t)row * DIM);
    o2[2 * t]     = __floats2half2_rn((v.x - mu) * inv * gv.x + bv.x,
                                      (v.y - mu) * inv * gv.y + bv.y);
    o2[2 * t + 1] = __floats2half2_rn((v.z - mu) * inv * gv.z + bv.z,
                                      (v.w - mu) * inv * gv.w + bv.w);
}

// ==================== fp16 GEMM: CTA 128x256, warp 64x64, pipelined frags ====
// mode: 0 = bias (half out), 1 = bias+gelu (half out), 2 = bias+residual (fp32 out)
#define BM    128
#define BN    256
#define KCH   64
#define SKH   72
#define A_TILE_H (BM * SKH)
#define B_TILE_H (BN * SKH)
#define STAGE_H (A_TILE_H + B_TILE_H)
#define N_STG 3
#define GEMM_SMEM (N_STG * STAGE_H * 2)   // 165888 bytes

__global__ __launch_bounds__(256, 1)
void h16_gemm(int M, int N, int K, int lda, int ldb,
              const __half* __restrict__ A0, const __half* __restrict__ Bt0,
              const float* __restrict__ bias0, const float* __restrict__ res,
              void* __restrict__ C0, int mode,
              const __half* __restrict__ A1, const __half* __restrict__ Bt1,
              const float* __restrict__ bias1, void* __restrict__ C1,
              const __half* __restrict__ A2, const __half* __restrict__ Bt2,
              const float* __restrict__ bias2, void* __restrict__ C2, int rows2)
{
    extern __shared__ __half smh[];

    const __half* A = A0; const __half* Bt = Bt0;
    const float* bias = bias0; void* Cv = C0;
    if (blockIdx.z == 1) { A = A1; Bt = Bt1; bias = bias1; Cv = C1; }
    else if (blockIdx.z == 2) {
        if ((int)blockIdx.y * BM >= rows2) return;
        A = A2; Bt = Bt2; bias = bias2; Cv = C2;
    }

    int tid = threadIdx.x;
    int lane = tid & 31;
    int warp = tid >> 5;
    int warp_m = (warp & 1) * 64;
    int warp_n = (warp >> 1) * 64;
    int r = lane >> 2;
    int c = lane & 3;

    int ctaM = blockIdx.y * BM;
    int ctaN = blockIdx.x * BN;

    const __half* gA = A  + (size_t)ctaM * lda;
    const __half* gB = Bt + (size_t)ctaN * ldb;

    int ldRow = tid >> 3;
    int ldCh  = (tid & 7) * 8;

    const int nk = K / KCH;

    uint32_t smb = (uint32_t)__cvta_generic_to_shared(smh);
    int aRowSel = lane & 15;
    int aKSel   = (lane >> 4) * 8;
    int bNSel   = (lane & 7) + ((lane >> 4) << 3);
    int bKSel   = ((lane >> 3) & 1) * 8;
    uint32_t aBase = smb + (uint32_t)(((warp_m + aRowSel) * SKH + aKSel) * 2);
    uint32_t bBase = smb + (uint32_t)((A_TILE_H + (warp_n + bNSel) * SKH + bKSel) * 2);

    #define ISSUE_STAGE(s, k0)                                                     \
    do {                                                                           \
        __half* sA_ = smh + (s) * STAGE_H;                                         \
        __half* sB_ = sA_ + A_TILE_H;                                              \
        const __half* a_ = gA + (k0);                                              \
        const __half* b_ = gB + (k0);                                              \
        _Pragma("unroll")                                                          \
        for (int j = 0; j < 4; j++) {                                              \
            int row = ldRow + j * 32;                                              \
            cp16(sA_ + (size_t)row * SKH + ldCh, a_ + (size_t)row * lda + ldCh);   \
        }                                                                          \
        _Pragma("unroll")                                                          \
        for (int j = 0; j < 8; j++) {                                              \
            int row = ldRow + j * 32;                                              \
            cp16(sB_ + (size_t)row * SKH + ldCh, b_ + (size_t)row * ldb + ldCh);   \
        }                                                                          \
        asm volatile("cp.async.commit_group;");                                    \
    } while (0)

    // load fragments for k16-step ks from stage offset stOff into slot sel
    #define LOAD_FRAGS(sel, stOff, ks)                                             \
    do {                                                                           \
        uint32_t kOff_ = (uint32_t)((ks) * 16 * 2) + (stOff);                      \
        _Pragma("unroll")                                                          \
        for (int mt = 0; mt < 4; mt++)                                             \
            ldsm_x4(afb[sel][mt][0], afb[sel][mt][1], afb[sel][mt][2],             \
                    afb[sel][mt][3], aBase + kOff_ + (uint32_t)(mt * 16 * SKH * 2)); \
        _Pragma("unroll")                                                          \
        for (int np = 0; np < 4; np++)                                             \
            ldsm_x4(bfb[sel][2 * np][0], bfb[sel][2 * np][1],                      \
                    bfb[sel][2 * np + 1][0], bfb[sel][2 * np + 1][1],              \
                    bBase + kOff_ + (uint32_t)(np * 16 * SKH * 2));                \
    } while (0)

    ISSUE_STAGE(0, 0);
    if (nk > 1) ISSUE_STAGE(1, KCH);
    else        asm volatile("cp.async.commit_group;");

    float acc[4][8][4] = {};
    uint32_t afb[2][4][4], bfb[2][8][2];

    for (int kt = 0; kt < nk; kt++) {
        int buf = kt % N_STG;
        if (kt + 1 < nk) asm volatile("cp.async.wait_group 1;");
        else             asm volatile("cp.async.wait_group 0;");
        __syncthreads();

        if (kt + 2 < nk) {
            int s = (kt + 2) % N_STG;
            ISSUE_STAGE(s, (kt + 2) * KCH);
        }

        uint32_t stOff = (uint32_t)(buf * STAGE_H * 2);

        LOAD_FRAGS(0, stOff, 0);
        #pragma unroll
        for (int ks = 0; ks < 4; ks++) {
            int cur = ks & 1;
            if (ks < 3) LOAD_FRAGS(cur ^ 1, stOff, ks + 1);
            #pragma unroll
            for (int mt = 0; mt < 4; mt++)
                #pragma unroll
                for (int nt = 0; nt < 8; nt++)
                    mma_f16(acc[mt][nt], afb[cur][mt], bfb[cur][nt]);
        }
    }
    #undef ISSUE_STAGE
    #undef LOAD_FRAGS

    // ---- epilogue ----
    float*  Cf = (float*)Cv;
    __half* Ch = (__half*)Cv;
    #pragma unroll
    for (int mt = 0; mt < 4; mt++) {
        #pragma unroll
        for (int nt = 0; nt < 8; nt++) {
            int row = ctaM + warp_m + mt * 16 + r;
            int col = ctaN + warp_n + nt * 8 + 2 * c;
            float b0 = bias[col], b1 = bias[col + 1];
            float v0 = acc[mt][nt][0] + b0;
            float v1 = acc[mt][nt][1] + b1;
            float v2 = acc[mt][nt][2] + b0;
            float v3 = acc[mt][nt][3] + b1;
            if (mode == 2) {
                const float* r0 = res + (size_t)row * N + col;
                const float* r1 = res + (size_t)(row + 8) * N + col;
                v0 += r0[0]; v1 += r0[1];
                v2 += r1[0]; v3 += r1[1];
                *(float2*)(Cf + (size_t)row * N + col)       = make_float2(v0, v1);
                *(float2*)(Cf + (size_t)(row + 8) * N + col) = make_float2(v2, v3);
            } else {
                if (mode == 1) {
                    v0 = gelu_exact(v0); v1 = gelu_exact(v1);
                    v2 = gelu_exact(v2); v3 = gelu_exact(v3);
                }
                *(__half2*)(Ch + (size_t)row * N + col)       = __floats2half2_rn(v0, v1);
                *(__half2*)(Ch + (size_t)(row + 8) * N + col) = __floats2half2_rn(v2, v3);
            }
        }
    }
}

// ==================== fp16 flash attention v4 (unchanged, R15) ================
#define BQ_T   256
#define TILE_K 64
#define SKKH 72
#define SKVH 72
#define NT_KV (NK / TILE_K)
#define ATT_SMEM ((3*TILE_K*SKKH + 3*TILE_K*SKVH) * 2)   // 55296 B

__global__ __launch_bounds__(256, 1)
void attn_mma(const __half* __restrict__ Q, const __half* __restrict__ Kg,
              const __half* __restrict__ Vg, __half* __restrict__ ctx)
{
    extern __shared__ __half smA[];
    __half* KsB = smA;
    __half* VsB = smA + 3 * TILE_K * SKKH;

    int b = blockIdx.z, h = blockIdx.y, qt = blockIdx.x;
    int tid = threadIdx.x, lane = tid & 31, w = tid >> 5;
    int r = lane >> 2, c = lane & 3;

    const __half* Qb = Q  + ((size_t)(b * NQ + qt * BQ_T)) * DIM + h * HD;
    const __half* Kb = Kg + ((size_t)b * NK) * DIM + h * HD;
    const __half* Vb = Vg + ((size_t)b * NK) * DIM + h * HD;

    #define ATT_ISSUE(s, kt_)                                                      \
    do {                                                                           \
        const __half* kp_ = Kb + (size_t)(kt_) * TILE_K * DIM;                     \
        const __half* vp_ = Vb + (size_t)(kt_) * TILE_K * DIM;                     \
        __half* Kd_ = KsB + (s) * TILE_K * SKKH;                                   \
        __half* Vd_ = VsB + (s) * TILE_K * SKVH;                                   \
        _Pragma("unroll")                                                          \
        for (int i = 0; i < 2; i++) {                                              \
            int idx = tid + i * 256;                                               \
            int row = idx >> 3, ch = (idx & 7) * 8;                                \
            cp16(&Kd_[row * SKKH + ch], kp_ + (size_t)row * DIM + ch);             \
            cp16(&Vd_[row * SKVH + ch], vp_ + (size_t)row * DIM + ch);             \
        }                                                                          \
        asm volatile("cp.async.commit_group;");                                    \
    } while (0)

    ATT_ISSUE(0, 0);
    ATT_ISSUE(1, 1);

    uint32_t qf0[4][4], qf1[4][4];
    {
        const float qs = 0.125f * 1.4426950408889634f;
        const __half2 sc = __floats2half2_rn(qs, qs);
        #pragma unroll
        for (int blk = 0; blk < 2; blk++) {
            const __half* q0 = Qb + (size_t)(w * 32 + blk * 16 + r) * DIM;
            const __half* q1 = q0 + 8 * DIM;
            #pragma unroll
            for (int kg = 0; kg < 4; kg++) {
                __half2 a0 = __hmul2(*(const __half2*)(q0 + kg * 16 + 2 * c), sc);
                __half2 a1 = __hmul2(*(const __half2*)(q1 + kg * 16 + 2 * c), sc);
                __half2 a2 = __hmul2(*(const __half2*)(q0 + kg * 16 + 2 * c + 8), sc);
                __half2 a3 = __hmul2(*(const __half2*)(q1 + kg * 16 + 2 * c + 8), sc);
                uint32_t* dst = blk ? qf1[kg] : qf0[kg];
                dst[0] = *(uint32_t*)&a0; dst[1] = *(uint32_t*)&a1;
                dst[2] = *(uint32_t*)&a2; dst[3] = *(uint32_t*)&a3;
            }
        }
    }

    float lSum0[4] = {}, lSum1[4] = {};
    const uint32_t bOnes[2] = { 0x3C003C00u, 0x3C003C00u };
    float accO0[8][4] = {}, accO1[8][4] = {};
    int l16 = lane & 15, nsel = lane >> 4;

    uint32_t smb = (uint32_t)__cvta_generic_to_shared(smA);
    int bNSel = (lane & 7) + ((lane >> 4) << 3);
    int bKSel = ((lane >> 3) & 1) * 8;
    uint32_t kFragBase = smb + (uint32_t)((bNSel * SKKH + bKSel) * 2);

    for (int kt = 0; kt < NT_KV; kt++) {
        int buf = kt % 3;
        if (kt + 1 < NT_KV) asm volatile("cp.async.wait_group 1;");
        else                asm volatile("cp.async.wait_group 0;");
        __syncthreads();

        if (kt + 2 < NT_KV) ATT_ISSUE((kt + 2) % 3, kt + 2);

        const __half* Vt = VsB + buf * TILE_K * SKVH;
        uint32_t kStage = (uint32_t)(buf * TILE_K * SKKH * 2);

        float accS0[8][4] = {}, accS1[8][4] = {};
        #pragma unroll
        for (int kg = 0; kg < 4; kg++) {
            uint32_t kOff = (uint32_t)(kg * 16 * 2);
            #pragma unroll
            for (int np = 0; np < 4; np++) {
                uint32_t bf0[2], bf1[2];
                ldsm_x4(bf0[0], bf0[1], bf1[0], bf1[1],
                        kFragBase + kStage + kOff + (uint32_t)(np * 16 * SKKH * 2));
                mma_f16(accS0[2 * np],     qf0[kg], bf0);
                mma_f16(accS0[2 * np + 1], qf0[kg], bf1);
                mma_f16(accS1[2 * np],     qf1[kg], bf0);
                mma_f16(accS1[2 * np + 1], qf1[kg], bf1);
            }
        }

        uint32_t pe0a[8], pe0b[8], pe1a[8], pe1b[8];
        #pragma unroll
        for (int nt = 0; nt < 8; nt++) {
            pe0a[nt] = ex2_h2(pack_h2(accS0[nt][0], accS0[nt][1]));
            pe0b[nt] = ex2_h2(pack_h2(accS0[nt][2], accS0[nt][3]));
            pe1a[nt] = ex2_h2(pack_h2(accS1[nt][0], accS1[nt][1]));
            pe1b[nt] = ex2_h2(pack_h2(accS1[nt][2], accS1[nt][3]));
        }

        #pragma unroll
        for (int kg = 0; kg < 4; kg++) {
            uint32_t af0[4], af1[4];
            af0[0] = pe0a[2 * kg];     af0[1] = pe0b[2 * kg];
            af0[2] = pe0a[2 * kg + 1]; af0[3] = pe0b[2 * kg + 1];
            af1[0] = pe1a[2 * kg];     af1[1] = pe1b[2 * kg];
            af1[2] = pe1a[2 * kg + 1]; af1[3] = pe1b[2 * kg + 1];
            mma_f16(lSum0, af0, bOnes);
            mma_f16(lSum1, af1, bOnes);
            #pragma unroll
            for (int nt = 0; nt < 8; nt += 2) {
                uint32_t vaddr = (uint32_t)__cvta_generic_to_shared(
                    Vt + (size_t)(kg * 16 + l16) * SKVH + (nt + nsel) * 8);
                uint32_t b0, b1, b2, b3;
                ldsm_x4_trans(b0, b1, b2, b3, vaddr);
                uint32_t bfa[2] = { b0, b1 }, bfb[2] = { b2, b3 };
                mma_f16(accO0[nt], af0, bfa);
                mma_f16(accO0[nt + 1], af0, bfb);
                mma_f16(accO1[nt], af1, bfa);
                mma_f16(accO1[nt + 1], af1, bfb);
            }
        }
    }
    #undef ATT_ISSUE

    float iA0 = 1.f / lSum0[0], iA1 = 1.f / lSum0[2];
    float iB0 = 1.f / lSum1[0], iB1 = 1.f / lSum1[2];
    __half* Cb0 = ctx + ((size_t)(b * NQ + qt * BQ_T + w * 32)) * DIM + h * HD;
    __half* Cb1 = Cb0 + 16 * DIM;
    #pragma unroll
    for (int nt = 0; nt < 8; nt++) {
        *(__half2*)(Cb0 + (size_t)r * DIM + nt * 8 + 2 * c) =
            __floats2half2_rn(accO0[nt][0] * iA0, accO0[nt][1] * iA0);
        *(__half2*)(Cb0 + (size_t)(r + 8) * DIM + nt * 8 + 2 * c) =
            __floats2half2_rn(accO0[nt][2] * iA1, accO0[nt][3] * iA1);
        *(__half2*)(Cb1 + (size_t)r * DIM + nt * 8 + 2 * c) =
            __floats2half2_rn(accO1[nt][0] * iB0, accO1[nt][1] * iB0);
        *(__half2*)(Cb1 + (size_t)(r + 8) * DIM + nt * 8 + 2 * c) =
            __floats2half2_rn(accO1[nt][2] * iB1, accO1[nt][3] * iB1);
    }
}

// ==================== launch =================================================
extern "C" void kernel_launch(void* const* d_in, const int* in_sizes, int n_in,
                              void* d_out, int out_size)
{
    const float* tgt  = (const float*)d_in[0];
    const float* emb  = (const float*)d_in[1];
    const float* ln_g = (const float*)d_in[2];
    const float* ln_b = (const float*)d_in[3];
    const float* wq = (const float*)d_in[4];  const float* bq = (const float*)d_in[5];
    const float* wk = (const float*)d_in[6];  const float* bk = (const float*)d_in[7];
    const float* wv = (const float*)d_in[8];  const float* bv = (const float*)d_in[9];
    const float* wo = (const float*)d_in[10]; const float* bo = (const float*)d_in[11];
    const float* w1 = (const float*)d_in[12]; const float* b1 = (const float*)d_in[13];
    const float* w2 = (const float*)d_in[14]; const float* b2 = (const float*)d_in[15];
    float* out = (float*)d_out;

    __half *qn, *q, *k, *v, *ctx, *h1, *embh, *wqt, *wkt, *wvt, *wot, *w1t, *w2t;
    cudaGetSymbolAddress((void**)&qn,   g_qn);
    cudaGetSymbolAddress((void**)&q,    g_q);
    cudaGetSymbolAddress((void**)&k,    g_k);
    cudaGetSymbolAddress((void**)&v,    g_v);
    cudaGetSymbolAddress((void**)&ctx,  g_ctx);
    cudaGetSymbolAddress((void**)&h1,   g_h1);
    cudaGetSymbolAddress((void**)&embh, g_embh);
    cudaGetSymbolAddress((void**)&wqt,  g_wqt);
    cudaGetSymbolAddress((void**)&wkt,  g_wkt);
    cudaGetSymbolAddress((void**)&wvt,  g_wvt);
    cudaGetSymbolAddress((void**)&wot,  g_wot);
    cudaGetSymbolAddress((void**)&w1t,  g_w1t);
    cudaGetSymbolAddress((void**)&w2t,  g_w2t);

    cudaFuncSetAttribute(h16_gemm, cudaFuncAttributeMaxDynamicSharedMemorySize, GEMM_SMEM);
    cudaFuncSetAttribute(attn_mma, cudaFuncAttributeMaxDynamicSharedMemorySize, ATT_SMEM);

    // 0) prep
    prep_kernel<<<13312, 256>>>(wq, wk, wv, wo, w1, w2, emb,
                                wqt, wkt, wvt, wot, w1t, w2t, embh);

    // 1) qn = LN(tgt)
    ln_kernel<<<MQ, 256>>>(tgt, ln_g, ln_b, qn);

    // 2-4) K,V,Q fused
    h16_gemm<<<dim3(DIM / BN, MK / BM, 3), 256, GEMM_SMEM>>>(
        MK, DIM, DIM, DIM, DIM,
        embh, wkt, bk, nullptr, (void*)k, 0,
        embh, wvt, bv, (void*)v,
        qn,   wqt, bq, (void*)q, MQ);

    // 5) ctx = softmax(Q K^T / 8) V
    attn_mma<<<dim3(NQ / BQ_T, HEADS, BSZ), 256, ATT_SMEM>>>(q, k, v, ctx);

    // 6) tgt1 = tgt + ctx @ wo + bo -> d_out
    h16_gemm<<<dim3(DIM / BN, MQ / BM, 1), 256, GEMM_SMEM>>>(
        MQ, DIM, DIM, DIM, DIM,
        ctx, wot, bo, tgt, (void*)out, 2,
        ctx, wot, bo, (void*)out,
        ctx, wot, bo, (void*)out, MQ);

    // 7) h_in = LN(tgt1)
    ln_kernel<<<MQ, 256>>>(out, ln_g, ln_b, qn);

    // 8) h1 = gelu(h_in @ w1 + b1)
    h16_gemm<<<dim3(HIDDEN / BN, MQ / BM, 1), 256, GEMM_SMEM>>>(
        MQ, HIDDEN, DIM, DIM, DIM,
        qn, w1t, b1, nullptr, (void*)h1, 1,
        qn, w1t, b1, (void*)h1,
        qn, w1t, b1, (void*)h1, MQ);

    // 9) out = tgt1 + h1 @ w2 + b2  (direct, single wave of 128 CTAs)
    h16_gemm<<<dim3(DIM / BN, MQ / BM, 1), 256, GEMM_SMEM>>>(
        MQ, DIM, HIDDEN, HIDDEN, HIDDEN,
        h1, w2t, b2, out, (void*)out, 2,
        h1, w2t, b2, (void*)out,
        h1, w2t, b2, (void*)out, MQ);
}